// round 1
// baseline (speedup 1.0000x reference)
#include <cuda_runtime.h>
#include <cuda_bf16.h>
#include <cstdint>

// Problem constants
#define BATCH 4
#define L_SEQ 2048
#define HID   1024
#define NST   16
#define XPW   (2*NST + HID)   // 1056
#define MROWS (BATCH * L_SEQ) // 8192

// Intermediate buffers (device globals: no allocation allowed)
__device__ float g_xp[(size_t)MROWS * XPW];  // x @ Wx^T (softplus applied to cols >= 32)
__device__ float g_y [(size_t)MROWS * HID];  // scan output

// ---------------------------------------------------------------------------
// helpers
// ---------------------------------------------------------------------------
__device__ __forceinline__ uint32_t smem_u32(const void* p) {
    return (uint32_t)__cvta_generic_to_shared(p);
}
__device__ __forceinline__ void cp_async16(uint32_t dst, const void* src) {
    asm volatile("cp.async.cg.shared.global [%0], [%1], 16;\n" :: "r"(dst), "l"(src) : "memory");
}
__device__ __forceinline__ void cp_commit() {
    asm volatile("cp.async.commit_group;\n" ::: "memory");
}
__device__ __forceinline__ void cp_wait1() {
    asm volatile("cp.async.wait_group 1;\n" ::: "memory");
}
__device__ __forceinline__ float ex2_approx(float v) {
    float r;
    asm("ex2.approx.ftz.f32 %0, %1;" : "=f"(r) : "f"(v));
    return r;
}
__device__ __forceinline__ float softplus_f(float z) {
    // accurate softplus: log1p(exp(-|z|)) + max(z,0)
    return log1pf(expf(-fabsf(z))) + fmaxf(z, 0.0f);
}

// ---------------------------------------------------------------------------
// SGEMM (NT): Out[m,n] = sum_k X[m,k] * W[n,k]
// X: M x K row-major; W: N x K row-major; Out: M x N row-major.
// Cols >= softplus_from get softplus applied in the epilogue.
// BM=128, BN=64, BK=16, 256 threads, 8x4 per-thread tile.
// ---------------------------------------------------------------------------
#define GBM 128
#define GBN 64
#define GBK 16

__global__ __launch_bounds__(256) void sgemm_nt(
    const float* __restrict__ X, const float* __restrict__ W,
    float* __restrict__ Out, int M, int Nn, int K, int softplus_from)
{
    __shared__ float As[GBK][GBM + 4];
    __shared__ float Bs[GBK][GBN + 4];

    const int tid = threadIdx.x;
    const int bm = blockIdx.y * GBM;
    const int bn = blockIdx.x * GBN;
    const int tx = tid & 15;   // n-dir (x4)
    const int ty = tid >> 4;   // m-dir (x8)

    float acc[8][4];
#pragma unroll
    for (int i = 0; i < 8; i++)
#pragma unroll
        for (int j = 0; j < 4; j++) acc[i][j] = 0.0f;

    const int lrow = tid >> 2;        // 0..63
    const int lc4  = (tid & 3) * 4;   // 0,4,8,12

    const float* Xb = X + (size_t)bm * K;

    for (int k0 = 0; k0 < K; k0 += GBK) {
        // X tile: 128 x 16 (two rows per thread), transposed into As
#pragma unroll
        for (int r = 0; r < 2; r++) {
            int row = lrow + r * 64;
            float4 v = *reinterpret_cast<const float4*>(&Xb[(size_t)row * K + k0 + lc4]);
            As[lc4 + 0][row] = v.x;
            As[lc4 + 1][row] = v.y;
            As[lc4 + 2][row] = v.z;
            As[lc4 + 3][row] = v.w;
        }
        // W tile: 64 x 16, transposed into Bs (guard N)
        {
            int row = lrow;
            float4 v = make_float4(0.f, 0.f, 0.f, 0.f);
            if (bn + row < Nn)
                v = *reinterpret_cast<const float4*>(&W[(size_t)(bn + row) * K + k0 + lc4]);
            Bs[lc4 + 0][row] = v.x;
            Bs[lc4 + 1][row] = v.y;
            Bs[lc4 + 2][row] = v.z;
            Bs[lc4 + 3][row] = v.w;
        }
        __syncthreads();

#pragma unroll
        for (int kk = 0; kk < GBK; kk++) {
            float4 a0 = *reinterpret_cast<const float4*>(&As[kk][ty * 8]);
            float4 a1 = *reinterpret_cast<const float4*>(&As[kk][ty * 8 + 4]);
            float4 b0 = *reinterpret_cast<const float4*>(&Bs[kk][tx * 4]);
            float a[8] = {a0.x, a0.y, a0.z, a0.w, a1.x, a1.y, a1.z, a1.w};
            float bb[4] = {b0.x, b0.y, b0.z, b0.w};
#pragma unroll
            for (int i = 0; i < 8; i++)
#pragma unroll
                for (int j = 0; j < 4; j++)
                    acc[i][j] = fmaf(a[i], bb[j], acc[i][j]);
        }
        __syncthreads();
    }

    // epilogue
#pragma unroll
    for (int i = 0; i < 8; i++) {
        int m = bm + ty * 8 + i;
#pragma unroll
        for (int j = 0; j < 4; j++) {
            int c = bn + tx * 4 + j;
            if (c < Nn) {
                float v = acc[i][j];
                if (c >= softplus_from) v = softplus_f(v);
                Out[(size_t)m * Nn + c] = v;
            }
        }
    }
}

// ---------------------------------------------------------------------------
// Selective scan.
// Block = 128 threads, handles one batch b and 32 h-channels.
// Warp: 8 h-channels; each h covered by 4 lanes (s = lane&3), 4 states each.
// Δ/x/B/C staged in 32-step chunks via cp.async double buffering.
// ---------------------------------------------------------------------------
#define CL 32                 // chunk length (steps)
#define NCH (L_SEQ / CL)      // 64 chunks

__global__ __launch_bounds__(128) void scan_kernel(
    const float* __restrict__ xp, const float* __restrict__ x,
    const float* __restrict__ A_log, const float* __restrict__ D,
    float* __restrict__ y)
{
    __shared__ __align__(16) float sD[2][CL][32];
    __shared__ __align__(16) float sX[2][CL][32];
    __shared__ __align__(16) float sB[2][CL][16];
    __shared__ __align__(16) float sC[2][CL][16];

    const int tid = threadIdx.x;
    const int b = blockIdx.x >> 5;
    const int hbase = (blockIdx.x & 31) * 32;
    const int lane = tid & 31;
    const int w = tid >> 5;
    const int s = lane & 3;                 // state group 0..3
    const int hl = (w << 3) | (lane >> 2);  // local h index 0..31
    const int h = hbase + hl;

    // per-thread state: 4 of the 16 SSM states
    float a2[4], hs[4];
#pragma unroll
    for (int i = 0; i < 4; i++) {
        a2[i] = -expf(A_log[s * 4 + i]) * 1.4426950408889634f; // A * log2(e)
        hs[i] = 0.0f;
    }
    const float Dv = D[h];

    const float* xp_b = xp + (size_t)b * L_SEQ * XPW;
    const float* x_b  = x  + (size_t)b * L_SEQ * HID;
    float*       y_b  = y  + (size_t)b * L_SEQ * HID;

    // --- chunk loader (all cp.async 16B; every address is 16B aligned) ---
    auto load_chunk = [&](int c, int buf) {
        const int l0 = c * CL;
        // sD / sX: 32 rows x 128B = 256 16B lines -> 2 per thread each
#pragma unroll
        for (int r = 0; r < 2; r++) {
            int idx = tid + r * 128;
            int row = idx >> 3;
            int col = (idx & 7) * 4;
            cp_async16(smem_u32(&sD[buf][row][col]),
                       &xp_b[(size_t)(l0 + row) * XPW + 2 * NST + hbase + col]);
            cp_async16(smem_u32(&sX[buf][row][col]),
                       &x_b[(size_t)(l0 + row) * HID + hbase + col]);
        }
        // sB / sC: 32 rows x 64B = 128 16B lines -> 1 per thread each
        {
            int row = tid >> 2;
            int col = (tid & 3) * 4;
            cp_async16(smem_u32(&sB[buf][row][col]),
                       &xp_b[(size_t)(l0 + row) * XPW + col]);
            cp_async16(smem_u32(&sC[buf][row][col]),
                       &xp_b[(size_t)(l0 + row) * XPW + NST + col]);
        }
    };

    load_chunk(0, 0);
    cp_commit();

    int buf = 0;
    for (int c = 0; c < NCH; c++) {
        if (c + 1 < NCH) load_chunk(c + 1, buf ^ 1);
        cp_commit();          // (possibly empty) group keeps wait_group math uniform
        cp_wait1();           // chunk c's group is complete
        __syncthreads();

        const int l0 = c * CL;
#pragma unroll 8
        for (int li = 0; li < CL; li++) {
            float dt = sD[buf][li][hl];
            float xv = sX[buf][li][hl];
            float4 Bv = *reinterpret_cast<const float4*>(&sB[buf][li][s * 4]);
            float4 Cv = *reinterpret_cast<const float4*>(&sC[buf][li][s * 4]);
            float dx = dt * xv;

            float yv;
            hs[0] = fmaf(ex2_approx(dt * a2[0]), hs[0], dx * Bv.x); yv = hs[0] * Cv.x;
            hs[1] = fmaf(ex2_approx(dt * a2[1]), hs[1], dx * Bv.y); yv = fmaf(hs[1], Cv.y, yv);
            hs[2] = fmaf(ex2_approx(dt * a2[2]), hs[2], dx * Bv.z); yv = fmaf(hs[2], Cv.z, yv);
            hs[3] = fmaf(ex2_approx(dt * a2[3]), hs[3], dx * Bv.w); yv = fmaf(hs[3], Cv.w, yv);

            // reduce over the 4 state groups (lanes differing in bits 0,1)
            yv += __shfl_xor_sync(0xffffffffu, yv, 1);
            yv += __shfl_xor_sync(0xffffffffu, yv, 2);

            if (s == 0)
                y_b[(size_t)(l0 + li) * HID + h] = fmaf(Dv, xv, yv);
        }
        __syncthreads();   // protect buf before it is refilled at c+2
        buf ^= 1;
    }
}

// ---------------------------------------------------------------------------
// launch
// ---------------------------------------------------------------------------
extern "C" void kernel_launch(void* const* d_in, const int* in_sizes, int n_in,
                              void* d_out, int out_size)
{
    const float* x     = (const float*)d_in[0];
    const float* Wx    = (const float*)d_in[1];
    const float* A_log = (const float*)d_in[2];
    const float* D     = (const float*)d_in[3];
    const float* Wout  = (const float*)d_in[4];
    float* out = (float*)d_out;

    float *xp_ptr, *y_ptr;
    cudaGetSymbolAddress((void**)&xp_ptr, g_xp);
    cudaGetSymbolAddress((void**)&y_ptr, g_y);

    // GEMM1: xp = x @ Wx^T, softplus on cols >= 32
    dim3 blk(256);
    dim3 g1((XPW + GBN - 1) / GBN, MROWS / GBM);
    sgemm_nt<<<g1, blk>>>(x, Wx, xp_ptr, MROWS, XPW, HID, 2 * NST);

    // selective scan
    scan_kernel<<<BATCH * (HID / 32), 128>>>(xp_ptr, x, A_log, D, y_ptr);

    // GEMM2: out = y @ Wout^T
    dim3 g2(HID / GBN, MROWS / GBM);
    sgemm_nt<<<g2, blk>>>(y_ptr, Wout, out, MROWS, HID, HID, 1 << 30);
}

// round 3
// speedup vs baseline: 1.4884x; 1.4884x over previous
#include <cuda_runtime.h>
#include <cuda_bf16.h>
#include <cstdint>

// Problem constants
#define BATCH 4
#define L_SEQ 2048
#define HID   1024
#define NST   16
#define MROWS (BATCH * L_SEQ) // 8192

// ---------------------------------------------------------------------------
// Device-global scratch (no allocation allowed)
// ---------------------------------------------------------------------------
__device__ __nv_bfloat16 g_xhi[(size_t)MROWS * HID];
__device__ __nv_bfloat16 g_xlo[(size_t)MROWS * HID];
__device__ __nv_bfloat16 g_yhi[(size_t)MROWS * HID];
__device__ __nv_bfloat16 g_ylo[(size_t)MROWS * HID];
__device__ __nv_bfloat16 g_wdhi[(size_t)HID * HID];   // Wx rows 32..1055 (delta weights)
__device__ __nv_bfloat16 g_wdlo[(size_t)HID * HID];
__device__ __nv_bfloat16 g_wohi[(size_t)HID * HID];   // Wout
__device__ __nv_bfloat16 g_wolo[(size_t)HID * HID];
__device__ float g_dt[(size_t)MROWS * HID];           // softplus(delta)
__device__ float g_bc[(size_t)MROWS * 2 * NST];       // B,C columns

// ---------------------------------------------------------------------------
// helpers
// ---------------------------------------------------------------------------
__device__ __forceinline__ uint32_t smem_u32(const void* p) {
    return (uint32_t)__cvta_generic_to_shared(p);
}
__device__ __forceinline__ void cp_async16(uint32_t dst, const void* src) {
    asm volatile("cp.async.cg.shared.global [%0], [%1], 16;\n" :: "r"(dst), "l"(src) : "memory");
}
__device__ __forceinline__ void cp_commit() {
    asm volatile("cp.async.commit_group;\n" ::: "memory");
}
__device__ __forceinline__ void cp_wait1() {
    asm volatile("cp.async.wait_group 1;\n" ::: "memory");
}
__device__ __forceinline__ void cp_wait0() {
    asm volatile("cp.async.wait_group 0;\n" ::: "memory");
}
__device__ __forceinline__ float ex2_approx(float v) {
    float r;
    asm("ex2.approx.ftz.f32 %0, %1;" : "=f"(r) : "f"(v));
    return r;
}
__device__ __forceinline__ float softplus_f(float z) {
    return log1pf(expf(-fabsf(z))) + fmaxf(z, 0.0f);
}

// SW64 swizzle for 64-byte rows (BK=32 bf16): bits[5:4] ^= bits[8:7]
#define SWZ64(off) ((off) ^ (((off) >> 3) & 0x30))

#define LDSM_X4(r0, r1, r2, r3, addr) \
    asm volatile("ldmatrix.sync.aligned.m8n8.x4.shared.b16 {%0,%1,%2,%3}, [%4];" \
        : "=r"(r0), "=r"(r1), "=r"(r2), "=r"(r3) : "r"(addr))

#define MMA_BF16(c0, c1, c2, c3, a0, a1, a2, a3, b0, b1) \
    asm volatile("mma.sync.aligned.m16n8k16.row.col.f32.bf16.bf16.f32 " \
        "{%0,%1,%2,%3}, {%4,%5,%6,%7}, {%8,%9}, {%0,%1,%2,%3};" \
        : "+f"(c0), "+f"(c1), "+f"(c2), "+f"(c3) \
        : "r"(a0), "r"(a1), "r"(a2), "r"(a3), "r"(b0), "r"(b1))

// ---------------------------------------------------------------------------
// fp32 -> (bf16 hi, bf16 lo) split
// ---------------------------------------------------------------------------
__global__ __launch_bounds__(256) void split_bf16(
    const float* __restrict__ s, __nv_bfloat16* __restrict__ hi,
    __nv_bfloat16* __restrict__ lo, int n4)
{
    int i = blockIdx.x * blockDim.x + threadIdx.x;
    if (i >= n4) return;
    float4 v = reinterpret_cast<const float4*>(s)[i];
    __nv_bfloat16 h0 = __float2bfloat16_rn(v.x);
    __nv_bfloat16 h1 = __float2bfloat16_rn(v.y);
    __nv_bfloat16 h2 = __float2bfloat16_rn(v.z);
    __nv_bfloat16 h3 = __float2bfloat16_rn(v.w);
    __nv_bfloat16 l0 = __float2bfloat16_rn(v.x - __bfloat162float(h0));
    __nv_bfloat16 l1 = __float2bfloat16_rn(v.y - __bfloat162float(h1));
    __nv_bfloat16 l2 = __float2bfloat16_rn(v.z - __bfloat162float(h2));
    __nv_bfloat16 l3 = __float2bfloat16_rn(v.w - __bfloat162float(h3));
    __nv_bfloat162* H = reinterpret_cast<__nv_bfloat162*>(hi);
    __nv_bfloat162* L = reinterpret_cast<__nv_bfloat162*>(lo);
    __nv_bfloat162 a; a.x = h0; a.y = h1;
    __nv_bfloat162 b; b.x = h2; b.y = h3;
    __nv_bfloat162 c; c.x = l0; c.y = l1;
    __nv_bfloat162 d; d.x = l2; d.y = l3;
    H[2 * i] = a; H[2 * i + 1] = b;
    L[2 * i] = c; L[2 * i + 1] = d;
}

// ---------------------------------------------------------------------------
// bf16x3 GEMM via mma.sync (NT): Out[m,n] = sum_k A[m,k]*B[n,k], fp32-accurate.
// A = Ahi+Alo, B = Bhi+Blo. M=8192, N=1024, K=1024.
// CTA tile 128x128x32, 256 threads (8 warps, 2x4), warp tile 64x32.
// SW64-swizzled smem, cp.async double buffer.
// ---------------------------------------------------------------------------
#define TBK 32
#define NKS (HID / TBK)               // 32 K-stages
#define TILE_B (128 * 64)             // 8192 bytes per operand tile
#define STAGE_B (4 * TILE_B)          // 32768
#define SMEM_TOTAL_G (2 * STAGE_B)    // 65536

__global__ __launch_bounds__(256) void gemm_bf16_mma(
    const __nv_bfloat16* __restrict__ Ahi, const __nv_bfloat16* __restrict__ Alo,
    const __nv_bfloat16* __restrict__ Bhi, const __nv_bfloat16* __restrict__ Blo,
    float* __restrict__ Out, int do_softplus)
{
    extern __shared__ __align__(1024) uint8_t dsm[];
    const uint32_t sbase = smem_u32(dsm);
    const int t = threadIdx.x;
    const int lid = t & 31;
    const int wid = t >> 5;
    const int warpM = (wid >> 2) * 64;   // 0 or 64
    const int warpN = (wid & 3) * 32;    // 0..96
    const int bm = blockIdx.y * 128;
    const int bn = blockIdx.x * 128;

    const __nv_bfloat16* srcs[4] = {
        Ahi + (size_t)bm * HID, Alo + (size_t)bm * HID,
        Bhi + (size_t)bn * HID, Blo + (size_t)bn * HID };

    // stage loader: 4 tiles x 128 rows x 4 16B-segments = 2048 chunks / 256 thr
    auto load_stage = [&](int k0, uint32_t soff) {
#pragma unroll
        for (int tile = 0; tile < 4; tile++) {
            const __nv_bfloat16* sp = srcs[tile] + k0;
            uint32_t dbase = sbase + soff + tile * TILE_B;
#pragma unroll
            for (int i = 0; i < 2; i++) {
                int u = t + i * 256;           // 0..511
                int row = u >> 2;
                int seg = u & 3;
                uint32_t off = (uint32_t)(row * 64 + seg * 16);
                cp_async16(dbase + SWZ64(off), sp + (size_t)row * HID + seg * 8);
            }
        }
    };

    float acc[4][4][4];
#pragma unroll
    for (int i = 0; i < 4; i++)
#pragma unroll
        for (int j = 0; j < 4; j++)
#pragma unroll
            for (int q = 0; q < 4; q++) acc[i][j][q] = 0.0f;

    // precomputed lane addressing offsets (within a tile, before swizzle)
    const int a_row = (lid & 15);
    const int a_khalf = (lid >> 4) << 4;       // 0 or 16 bytes
    const int b_q = lid >> 3;                   // 0..3
    const int b_row = ((b_q >> 1) << 3) + (lid & 7);  // n row within 16
    const int b_khalf = (b_q & 1) << 4;         // 0 or 16 bytes

    load_stage(0, 0);
    cp_commit();

    for (int k = 0; k < NKS; k++) {
        const int buf = k & 1;
        if (k + 1 < NKS) {
            load_stage((k + 1) * TBK, (uint32_t)(buf ^ 1) * STAGE_B);
            cp_commit();
            cp_wait1();
        } else {
            cp_wait0();
        }
        __syncthreads();

        const uint32_t sb = sbase + (uint32_t)buf * STAGE_B;
#pragma unroll
        for (int kk = 0; kk < 2; kk++) {
            uint32_t ah[16], al[16], bh[8], bl[8];
            // A fragments (hi & lo): 4 m-tiles each
#pragma unroll
            for (int mt = 0; mt < 4; mt++) {
                uint32_t off = (uint32_t)((warpM + mt * 16 + a_row) * 64 + kk * 32 + a_khalf);
                uint32_t sw = SWZ64(off);
                LDSM_X4(ah[mt*4+0], ah[mt*4+1], ah[mt*4+2], ah[mt*4+3], sb + 0 * TILE_B + sw);
                LDSM_X4(al[mt*4+0], al[mt*4+1], al[mt*4+2], al[mt*4+3], sb + 1 * TILE_B + sw);
            }
            // B fragments (hi & lo): 2 x ldmatrix.x4 cover 4 n-tiles
#pragma unroll
            for (int g = 0; g < 2; g++) {
                uint32_t off = (uint32_t)((warpN + g * 16 + b_row) * 64 + kk * 32 + b_khalf);
                uint32_t sw = SWZ64(off);
                LDSM_X4(bh[g*4+0], bh[g*4+1], bh[g*4+2], bh[g*4+3], sb + 2 * TILE_B + sw);
                LDSM_X4(bl[g*4+0], bl[g*4+1], bl[g*4+2], bl[g*4+3], sb + 3 * TILE_B + sw);
            }
            // 3-term compensated MMAs
#pragma unroll
            for (int mt = 0; mt < 4; mt++) {
#pragma unroll
                for (int nt = 0; nt < 4; nt++) {
                    float* c = acc[mt][nt];
                    MMA_BF16(c[0], c[1], c[2], c[3],
                             ah[mt*4+0], ah[mt*4+1], ah[mt*4+2], ah[mt*4+3],
                             bh[nt*2+0], bh[nt*2+1]);
                    MMA_BF16(c[0], c[1], c[2], c[3],
                             ah[mt*4+0], ah[mt*4+1], ah[mt*4+2], ah[mt*4+3],
                             bl[nt*2+0], bl[nt*2+1]);
                    MMA_BF16(c[0], c[1], c[2], c[3],
                             al[mt*4+0], al[mt*4+1], al[mt*4+2], al[mt*4+3],
                             bh[nt*2+0], bh[nt*2+1]);
                }
            }
        }
        __syncthreads();
    }

    // epilogue
    const int tq = lid >> 2;
    const int tr = (lid & 3) * 2;
#pragma unroll
    for (int mt = 0; mt < 4; mt++) {
#pragma unroll
        for (int nt = 0; nt < 4; nt++) {
            float* c = acc[mt][nt];
            int m0 = bm + warpM + mt * 16 + tq;
            int n0 = bn + warpN + nt * 8 + tr;
            float v0 = c[0], v1 = c[1], v2 = c[2], v3 = c[3];
            if (do_softplus) {
                v0 = softplus_f(v0); v1 = softplus_f(v1);
                v2 = softplus_f(v2); v3 = softplus_f(v3);
            }
            float2* p0 = reinterpret_cast<float2*>(&Out[(size_t)m0 * HID + n0]);
            float2* p1 = reinterpret_cast<float2*>(&Out[(size_t)(m0 + 8) * HID + n0]);
            *p0 = make_float2(v0, v1);
            *p1 = make_float2(v2, v3);
        }
    }
}

// ---------------------------------------------------------------------------
// fp32 SGEMM (NT) — only for the small B/C projection (N=32)
// ---------------------------------------------------------------------------
#define GBM 128
#define GBN 64
#define GBK 16

__global__ __launch_bounds__(256) void sgemm_nt(
    const float* __restrict__ X, const float* __restrict__ W,
    float* __restrict__ Out, int M, int Nn, int K)
{
    __shared__ float As[GBK][GBM + 4];
    __shared__ float Bs[GBK][GBN + 4];

    const int tid = threadIdx.x;
    const int bm = blockIdx.y * GBM;
    const int bn = blockIdx.x * GBN;
    const int tx = tid & 15;
    const int ty = tid >> 4;

    float acc[8][4];
#pragma unroll
    for (int i = 0; i < 8; i++)
#pragma unroll
        for (int j = 0; j < 4; j++) acc[i][j] = 0.0f;

    const int lrow = tid >> 2;
    const int lc4  = (tid & 3) * 4;
    const float* Xb = X + (size_t)bm * K;

    for (int k0 = 0; k0 < K; k0 += GBK) {
#pragma unroll
        for (int r = 0; r < 2; r++) {
            int row = lrow + r * 64;
            float4 v = *reinterpret_cast<const float4*>(&Xb[(size_t)row * K + k0 + lc4]);
            As[lc4 + 0][row] = v.x; As[lc4 + 1][row] = v.y;
            As[lc4 + 2][row] = v.z; As[lc4 + 3][row] = v.w;
        }
        {
            int row = lrow;
            float4 v = make_float4(0.f, 0.f, 0.f, 0.f);
            if (bn + row < Nn)
                v = *reinterpret_cast<const float4*>(&W[(size_t)(bn + row) * K + k0 + lc4]);
            Bs[lc4 + 0][row] = v.x; Bs[lc4 + 1][row] = v.y;
            Bs[lc4 + 2][row] = v.z; Bs[lc4 + 3][row] = v.w;
        }
        __syncthreads();

#pragma unroll
        for (int kk = 0; kk < GBK; kk++) {
            float4 a0 = *reinterpret_cast<const float4*>(&As[kk][ty * 8]);
            float4 a1 = *reinterpret_cast<const float4*>(&As[kk][ty * 8 + 4]);
            float4 b0 = *reinterpret_cast<const float4*>(&Bs[kk][tx * 4]);
            float a[8] = {a0.x, a0.y, a0.z, a0.w, a1.x, a1.y, a1.z, a1.w};
            float bb[4] = {b0.x, b0.y, b0.z, b0.w};
#pragma unroll
            for (int i = 0; i < 8; i++)
#pragma unroll
                for (int j = 0; j < 4; j++)
                    acc[i][j] = fmaf(a[i], bb[j], acc[i][j]);
        }
        __syncthreads();
    }

#pragma unroll
    for (int i = 0; i < 8; i++) {
        int mm = bm + ty * 8 + i;
#pragma unroll
        for (int j = 0; j < 4; j++) {
            int c = bn + tx * 4 + j;
            if (c < Nn) Out[(size_t)mm * Nn + c] = acc[i][j];
        }
    }
}

// ---------------------------------------------------------------------------
// Selective scan; writes bf16 hi/lo directly (fused y split)
// ---------------------------------------------------------------------------
#define CL 32
#define NCH (L_SEQ / CL)

__global__ __launch_bounds__(128) void scan_kernel(
    const float* __restrict__ dt_g, const float* __restrict__ bc_g,
    const float* __restrict__ x, const float* __restrict__ A_log,
    const float* __restrict__ Dp,
    __nv_bfloat16* __restrict__ yhi, __nv_bfloat16* __restrict__ ylo)
{
    __shared__ __align__(16) float sD[2][CL][32];
    __shared__ __align__(16) float sX[2][CL][32];
    __shared__ __align__(16) float sB[2][CL][16];
    __shared__ __align__(16) float sC[2][CL][16];

    const int tid = threadIdx.x;
    const int b = blockIdx.x >> 5;
    const int hbase = (blockIdx.x & 31) * 32;
    const int lane = tid & 31;
    const int w = tid >> 5;
    const int s = lane & 3;
    const int hl = (w << 3) | (lane >> 2);
    const int h = hbase + hl;

    float a2[4], hs[4];
#pragma unroll
    for (int i = 0; i < 4; i++) {
        a2[i] = -expf(A_log[s * 4 + i]) * 1.4426950408889634f;
        hs[i] = 0.0f;
    }
    const float Dv = Dp[h];

    const float* dt_b = dt_g + (size_t)b * L_SEQ * HID;
    const float* bc_b = bc_g + (size_t)b * L_SEQ * 2 * NST;
    const float* x_b  = x    + (size_t)b * L_SEQ * HID;
    __nv_bfloat16* yh_b = yhi + (size_t)b * L_SEQ * HID;
    __nv_bfloat16* yl_b = ylo + (size_t)b * L_SEQ * HID;

    auto load_chunk = [&](int c, int buf) {
        const int l0 = c * CL;
#pragma unroll
        for (int r = 0; r < 2; r++) {
            int idx = tid + r * 128;
            int row = idx >> 3;
            int col = (idx & 7) * 4;
            cp_async16(smem_u32(&sD[buf][row][col]),
                       &dt_b[(size_t)(l0 + row) * HID + hbase + col]);
            cp_async16(smem_u32(&sX[buf][row][col]),
                       &x_b[(size_t)(l0 + row) * HID + hbase + col]);
        }
        {
            int row = tid >> 2;
            int col = (tid & 3) * 4;
            cp_async16(smem_u32(&sB[buf][row][col]),
                       &bc_b[(size_t)(l0 + row) * 2 * NST + col]);
            cp_async16(smem_u32(&sC[buf][row][col]),
                       &bc_b[(size_t)(l0 + row) * 2 * NST + NST + col]);
        }
    };

    load_chunk(0, 0);
    cp_commit();

    int buf = 0;
    for (int c = 0; c < NCH; c++) {
        if (c + 1 < NCH) load_chunk(c + 1, buf ^ 1);
        cp_commit();
        cp_wait1();
        __syncthreads();

        const int l0 = c * CL;
#pragma unroll 8
        for (int li = 0; li < CL; li++) {
            float dt = sD[buf][li][hl];
            float xv = sX[buf][li][hl];
            float4 Bv = *reinterpret_cast<const float4*>(&sB[buf][li][s * 4]);
            float4 Cv = *reinterpret_cast<const float4*>(&sC[buf][li][s * 4]);
            float dx = dt * xv;

            float yv;
            hs[0] = fmaf(ex2_approx(dt * a2[0]), hs[0], dx * Bv.x); yv = hs[0] * Cv.x;
            hs[1] = fmaf(ex2_approx(dt * a2[1]), hs[1], dx * Bv.y); yv = fmaf(hs[1], Cv.y, yv);
            hs[2] = fmaf(ex2_approx(dt * a2[2]), hs[2], dx * Bv.z); yv = fmaf(hs[2], Cv.z, yv);
            hs[3] = fmaf(ex2_approx(dt * a2[3]), hs[3], dx * Bv.w); yv = fmaf(hs[3], Cv.w, yv);

            yv += __shfl_xor_sync(0xffffffffu, yv, 1);
            yv += __shfl_xor_sync(0xffffffffu, yv, 2);

            if (s == 0) {
                float yy = fmaf(Dv, xv, yv);
                __nv_bfloat16 hh = __float2bfloat16_rn(yy);
                size_t o = (size_t)(l0 + li) * HID + h;
                yh_b[o] = hh;
                yl_b[o] = __float2bfloat16_rn(yy - __bfloat162float(hh));
            }
        }
        __syncthreads();
        buf ^= 1;
    }
}

// ---------------------------------------------------------------------------
// launch
// ---------------------------------------------------------------------------
extern "C" void kernel_launch(void* const* d_in, const int* in_sizes, int n_in,
                              void* d_out, int out_size)
{
    const float* x     = (const float*)d_in[0];
    const float* Wx    = (const float*)d_in[1];
    const float* A_log = (const float*)d_in[2];
    const float* D     = (const float*)d_in[3];
    const float* Wout  = (const float*)d_in[4];
    float* out = (float*)d_out;

    __nv_bfloat16 *xhi, *xlo, *yhi, *ylo, *wdhi, *wdlo, *wohi, *wolo;
    float *dt_p, *bc_p;
    cudaGetSymbolAddress((void**)&xhi, g_xhi);
    cudaGetSymbolAddress((void**)&xlo, g_xlo);
    cudaGetSymbolAddress((void**)&yhi, g_yhi);
    cudaGetSymbolAddress((void**)&ylo, g_ylo);
    cudaGetSymbolAddress((void**)&wdhi, g_wdhi);
    cudaGetSymbolAddress((void**)&wdlo, g_wdlo);
    cudaGetSymbolAddress((void**)&wohi, g_wohi);
    cudaGetSymbolAddress((void**)&wolo, g_wolo);
    cudaGetSymbolAddress((void**)&dt_p, g_dt);
    cudaGetSymbolAddress((void**)&bc_p, g_bc);

    cudaFuncSetAttribute(gemm_bf16_mma, cudaFuncAttributeMaxDynamicSharedMemorySize, SMEM_TOTAL_G);

    // bf16 splits
    {
        int n4 = MROWS * HID / 4;
        split_bf16<<<(n4 + 255) / 256, 256>>>(x, xhi, xlo, n4);
        int w4 = HID * HID / 4;
        split_bf16<<<(w4 + 255) / 256, 256>>>(Wx + 2 * NST * HID, wdhi, wdlo, w4);
        split_bf16<<<(w4 + 255) / 256, 256>>>(Wout, wohi, wolo, w4);
    }

    // GEMM1a (tensor): dt = softplus(x @ Wdelta^T)   [8192 x 1024]
    gemm_bf16_mma<<<dim3(HID / 128, MROWS / 128), 256, SMEM_TOTAL_G>>>(
        xhi, xlo, wdhi, wdlo, dt_p, 1);

    // GEMM1b (fp32): bc = x @ Wbc^T   [8192 x 32]
    sgemm_nt<<<dim3(1, MROWS / GBM), 256>>>(x, Wx, bc_p, MROWS, 2 * NST, HID);

    // selective scan (writes yhi/ylo directly)
    scan_kernel<<<BATCH * (HID / 32), 128>>>(dt_p, bc_p, x, A_log, D, yhi, ylo);

    // GEMM2 (tensor): out = y @ Wout^T
    gemm_bf16_mma<<<dim3(HID / 128, MROWS / 128), 256, SMEM_TOTAL_G>>>(
        yhi, ylo, wohi, wolo, out, 0);
}

// round 6
// speedup vs baseline: 1.7930x; 1.2047x over previous
#include <cuda_runtime.h>
#include <cuda_bf16.h>
#include <cstdint>

// Problem constants
#define BATCH 4
#define L_SEQ 2048
#define HID   1024
#define NST   16
#define MROWS (BATCH * L_SEQ) // 8192

// ---------------------------------------------------------------------------
// Device-global scratch (zero-initialized; no allocation allowed)
// ---------------------------------------------------------------------------
__device__ __nv_bfloat16 g_xhi[(size_t)MROWS * HID];
__device__ __nv_bfloat16 g_xlo[(size_t)MROWS * HID];
__device__ __nv_bfloat16 g_yhi[(size_t)MROWS * HID];
__device__ __nv_bfloat16 g_ylo[(size_t)MROWS * HID];
__device__ __nv_bfloat16 g_wdhi[(size_t)HID * HID];    // Wx rows 32..1055 (delta)
__device__ __nv_bfloat16 g_wdlo[(size_t)HID * HID];
__device__ __nv_bfloat16 g_wohi[(size_t)HID * HID];    // Wout
__device__ __nv_bfloat16 g_wolo[(size_t)HID * HID];
__device__ __nv_bfloat16 g_wbchi[(size_t)128 * HID];   // Wx rows 0..31, zero-padded to 128
__device__ __nv_bfloat16 g_wbclo[(size_t)128 * HID];
__device__ float g_dt[(size_t)MROWS * HID];            // softplus(delta)
__device__ float g_bc[(size_t)MROWS * 2 * NST];        // B,C columns

// ---------------------------------------------------------------------------
// helpers
// ---------------------------------------------------------------------------
__device__ __forceinline__ uint32_t smem_u32(const void* p) {
    return (uint32_t)__cvta_generic_to_shared(p);
}
__device__ __forceinline__ void cp_async16(uint32_t dst, const void* src) {
    asm volatile("cp.async.cg.shared.global [%0], [%1], 16;\n" :: "r"(dst), "l"(src) : "memory");
}
__device__ __forceinline__ void cp_commit() {
    asm volatile("cp.async.commit_group;\n" ::: "memory");
}
__device__ __forceinline__ void cp_wait1() {
    asm volatile("cp.async.wait_group 1;\n" ::: "memory");
}
__device__ __forceinline__ float ex2_approx(float v) {
    float r;
    asm("ex2.approx.ftz.f32 %0, %1;" : "=f"(r) : "f"(v));
    return r;
}
__device__ __forceinline__ float softplus_f(float z) {
    return log1pf(expf(-fabsf(z))) + fmaxf(z, 0.0f);
}

// SW64 swizzle for 64-byte rows (BK=32 bf16)
#define SWZ64(off) ((off) ^ (((off) >> 3) & 0x30))

#define LDSM_X4(r0, r1, r2, r3, addr) \
    asm volatile("ldmatrix.sync.aligned.m8n8.x4.shared.b16 {%0,%1,%2,%3}, [%4];" \
        : "=r"(r0), "=r"(r1), "=r"(r2), "=r"(r3) : "r"(addr))

#define MMA_BF16(c0, c1, c2, c3, a0, a1, a2, a3, b0, b1) \
    asm volatile("mma.sync.aligned.m16n8k16.row.col.f32.bf16.bf16.f32 " \
        "{%0,%1,%2,%3}, {%4,%5,%6,%7}, {%8,%9}, {%0,%1,%2,%3};" \
        : "+f"(c0), "+f"(c1), "+f"(c2), "+f"(c3) \
        : "r"(a0), "r"(a1), "r"(a2), "r"(a3), "r"(b0), "r"(b1))

// ---------------------------------------------------------------------------
// fp32 -> (bf16 hi, bf16 lo) split
// ---------------------------------------------------------------------------
__global__ __launch_bounds__(256) void split_bf16(
    const float* __restrict__ s, __nv_bfloat16* __restrict__ hi,
    __nv_bfloat16* __restrict__ lo, int n4)
{
    int i = blockIdx.x * blockDim.x + threadIdx.x;
    if (i >= n4) return;
    float4 v = reinterpret_cast<const float4*>(s)[i];
    __nv_bfloat16 h0 = __float2bfloat16_rn(v.x);
    __nv_bfloat16 h1 = __float2bfloat16_rn(v.y);
    __nv_bfloat16 h2 = __float2bfloat16_rn(v.z);
    __nv_bfloat16 h3 = __float2bfloat16_rn(v.w);
    __nv_bfloat16 l0 = __float2bfloat16_rn(v.x - __bfloat162float(h0));
    __nv_bfloat16 l1 = __float2bfloat16_rn(v.y - __bfloat162float(h1));
    __nv_bfloat16 l2 = __float2bfloat16_rn(v.z - __bfloat162float(h2));
    __nv_bfloat16 l3 = __float2bfloat16_rn(v.w - __bfloat162float(h3));
    __nv_bfloat162* H = reinterpret_cast<__nv_bfloat162*>(hi);
    __nv_bfloat162* L = reinterpret_cast<__nv_bfloat162*>(lo);
    __nv_bfloat162 a; a.x = h0; a.y = h1;
    __nv_bfloat162 b; b.x = h2; b.y = h3;
    __nv_bfloat162 c; c.x = l0; c.y = l1;
    __nv_bfloat162 d; d.x = l2; d.y = l3;
    H[2 * i] = a; H[2 * i + 1] = b;
    L[2 * i] = c; L[2 * i + 1] = d;
}

// ---------------------------------------------------------------------------
// bf16x3 GEMM via mma.sync (NT), fp32-accurate.
// CTA tile 128x128x32, 512 threads (16 warps, 4x4), warp tile 32x32.
// 3-stage cp.async pipeline, SW64 smem.
// blockIdx.x == 8 (GEMM1 only): B/C projection against zero-padded Wbc,
//   writes OutBC [M x 32], no softplus.
// ---------------------------------------------------------------------------
#define TBK 32
#define NKS (HID / TBK)               // 32 K-stages
#define TILE_B (128 * 64)             // 8192 bytes per operand tile
#define STAGE_B (4 * TILE_B)          // 32768
#define NSTAGE 3
#define SMEM_TOTAL_G (NSTAGE * STAGE_B)  // 98304

__global__ __launch_bounds__(512) void gemm_bf16_mma(
    const __nv_bfloat16* __restrict__ Ahi, const __nv_bfloat16* __restrict__ Alo,
    const __nv_bfloat16* __restrict__ Bhi, const __nv_bfloat16* __restrict__ Blo,
    const __nv_bfloat16* __restrict__ BChi, const __nv_bfloat16* __restrict__ BClo,
    float* __restrict__ Out, float* __restrict__ OutBC, int do_softplus)
{
    extern __shared__ __align__(1024) uint8_t dsm[];
    const uint32_t sbase = smem_u32(dsm);
    const int t = threadIdx.x;
    const int lid = t & 31;
    const int wid = t >> 5;
    const int warpM = (wid >> 2) * 32;   // 0,32,64,96
    const int warpN = (wid & 3) * 32;    // 0,32,64,96
    const int bm = blockIdx.y * 128;
    const bool bc = (blockIdx.x == 8);
    const int bn = bc ? 0 : blockIdx.x * 128;

    const __nv_bfloat16* srcs[4];
    srcs[0] = Ahi + (size_t)bm * HID;
    srcs[1] = Alo + (size_t)bm * HID;
    srcs[2] = (bc ? BChi : Bhi + (size_t)bn * HID);
    srcs[3] = (bc ? BClo : Blo + (size_t)bn * HID);

    // stage loader: 4 tiles x (128 rows x 4 segs of 16B) = 2048 chunks / 512 thr
    auto load_stage = [&](int k0, uint32_t soff) {
        const int row = t >> 2;
        const int seg = t & 3;
        const uint32_t off = SWZ64((uint32_t)(row * 64 + seg * 16));
        const size_t goff = (size_t)row * HID + seg * 8 + k0;
#pragma unroll
        for (int tile = 0; tile < 4; tile++)
            cp_async16(sbase + soff + tile * TILE_B + off, srcs[tile] + goff);
    };

    float acc[2][4][4];
#pragma unroll
    for (int i = 0; i < 2; i++)
#pragma unroll
        for (int j = 0; j < 4; j++)
#pragma unroll
            for (int q = 0; q < 4; q++) acc[i][j][q] = 0.0f;

    // lane addressing
    const int a_row = (lid & 15);
    const int a_khalf = (lid >> 4) << 4;
    const int b_q = lid >> 3;
    const int b_row = ((b_q >> 1) << 3) + (lid & 7);
    const int b_khalf = (b_q & 1) << 4;

    load_stage(0, 0);
    cp_commit();
    load_stage(TBK, STAGE_B);
    cp_commit();

    for (int k = 0; k < NKS; k++) {
        cp_wait1();              // stage k resident
        __syncthreads();         // everyone done with stage k-1
        if (k + 2 < NKS) load_stage((k + 2) * TBK, (uint32_t)((k + 2) % NSTAGE) * STAGE_B);
        cp_commit();

        const uint32_t sb = sbase + (uint32_t)(k % NSTAGE) * STAGE_B;
#pragma unroll
        for (int kk = 0; kk < 2; kk++) {
            uint32_t ah[8], al[8], bh[8], bl[8];
#pragma unroll
            for (int mt = 0; mt < 2; mt++) {
                uint32_t sw = SWZ64((uint32_t)((warpM + mt * 16 + a_row) * 64 + kk * 32 + a_khalf));
                LDSM_X4(ah[mt*4+0], ah[mt*4+1], ah[mt*4+2], ah[mt*4+3], sb + 0 * TILE_B + sw);
                LDSM_X4(al[mt*4+0], al[mt*4+1], al[mt*4+2], al[mt*4+3], sb + 1 * TILE_B + sw);
            }
#pragma unroll
            for (int g = 0; g < 2; g++) {
                uint32_t sw = SWZ64((uint32_t)((warpN + g * 16 + b_row) * 64 + kk * 32 + b_khalf));
                LDSM_X4(bh[g*4+0], bh[g*4+1], bh[g*4+2], bh[g*4+3], sb + 2 * TILE_B + sw);
                LDSM_X4(bl[g*4+0], bl[g*4+1], bl[g*4+2], bl[g*4+3], sb + 3 * TILE_B + sw);
            }
#pragma unroll
            for (int mt = 0; mt < 2; mt++) {
#pragma unroll
                for (int nt = 0; nt < 4; nt++) {
                    float* c = acc[mt][nt];
                    MMA_BF16(c[0], c[1], c[2], c[3],
                             ah[mt*4+0], ah[mt*4+1], ah[mt*4+2], ah[mt*4+3],
                             bh[nt*2+0], bh[nt*2+1]);
                    MMA_BF16(c[0], c[1], c[2], c[3],
                             ah[mt*4+0], ah[mt*4+1], ah[mt*4+2], ah[mt*4+3],
                             bl[nt*2+0], bl[nt*2+1]);
                    MMA_BF16(c[0], c[1], c[2], c[3],
                             al[mt*4+0], al[mt*4+1], al[mt*4+2], al[mt*4+3],
                             bh[nt*2+0], bh[nt*2+1]);
                }
            }
        }
    }

    // epilogue
    const int tq = lid >> 2;
    const int tr = (lid & 3) * 2;
#pragma unroll
    for (int mt = 0; mt < 2; mt++) {
#pragma unroll
        for (int nt = 0; nt < 4; nt++) {
            float* c = acc[mt][nt];
            int mrow = bm + warpM + mt * 16 + tq;
            int ncol = warpN + nt * 8 + tr;
            if (!bc) {
                float v0 = c[0], v1 = c[1], v2 = c[2], v3 = c[3];
                if (do_softplus) {
                    v0 = softplus_f(v0); v1 = softplus_f(v1);
                    v2 = softplus_f(v2); v3 = softplus_f(v3);
                }
                *reinterpret_cast<float2*>(&Out[(size_t)mrow * HID + bn + ncol]) = make_float2(v0, v1);
                *reinterpret_cast<float2*>(&Out[(size_t)(mrow + 8) * HID + bn + ncol]) = make_float2(v2, v3);
            } else if (ncol < 2 * NST) {
                *reinterpret_cast<float2*>(&OutBC[(size_t)mrow * (2 * NST) + ncol]) = make_float2(c[0], c[1]);
                *reinterpret_cast<float2*>(&OutBC[(size_t)(mrow + 8) * (2 * NST) + ncol]) = make_float2(c[2], c[3]);
            }
        }
    }
}

// ---------------------------------------------------------------------------
// Selective scan; writes bf16 hi/lo directly (fused y split)
// ---------------------------------------------------------------------------
#define CL 32
#define NCH (L_SEQ / CL)

__global__ __launch_bounds__(128) void scan_kernel(
    const float* __restrict__ dt_g, const float* __restrict__ bc_g,
    const float* __restrict__ x, const float* __restrict__ A_log,
    const float* __restrict__ Dp,
    __nv_bfloat16* __restrict__ yhi, __nv_bfloat16* __restrict__ ylo)
{
    __shared__ __align__(16) float sD[2][CL][32];
    __shared__ __align__(16) float sX[2][CL][32];
    __shared__ __align__(16) float sB[2][CL][16];
    __shared__ __align__(16) float sC[2][CL][16];

    const int tid = threadIdx.x;
    const int b = blockIdx.x >> 5;
    const int hbase = (blockIdx.x & 31) * 32;
    const int lane = tid & 31;
    const int w = tid >> 5;
    const int s = lane & 3;
    const int hl = (w << 3) | (lane >> 2);
    const int h = hbase + hl;

    float a2[4], hs[4];
#pragma unroll
    for (int i = 0; i < 4; i++) {
        a2[i] = -expf(A_log[s * 4 + i]) * 1.4426950408889634f;
        hs[i] = 0.0f;
    }
    const float Dv = Dp[h];

    const float* dt_b = dt_g + (size_t)b * L_SEQ * HID;
    const float* bc_b = bc_g + (size_t)b * L_SEQ * 2 * NST;
    const float* x_b  = x    + (size_t)b * L_SEQ * HID;
    __nv_bfloat16* yh_b = yhi + (size_t)b * L_SEQ * HID;
    __nv_bfloat16* yl_b = ylo + (size_t)b * L_SEQ * HID;

    auto load_chunk = [&](int c, int buf) {
        const int l0 = c * CL;
#pragma unroll
        for (int r = 0; r < 2; r++) {
            int idx = tid + r * 128;
            int row = idx >> 3;
            int col = (idx & 7) * 4;
            cp_async16(smem_u32(&sD[buf][row][col]),
                       &dt_b[(size_t)(l0 + row) * HID + hbase + col]);
            cp_async16(smem_u32(&sX[buf][row][col]),
                       &x_b[(size_t)(l0 + row) * HID + hbase + col]);
        }
        {
            int row = tid >> 2;
            int col = (tid & 3) * 4;
            cp_async16(smem_u32(&sB[buf][row][col]),
                       &bc_b[(size_t)(l0 + row) * 2 * NST + col]);
            cp_async16(smem_u32(&sC[buf][row][col]),
                       &bc_b[(size_t)(l0 + row) * 2 * NST + NST + col]);
        }
    };

    load_chunk(0, 0);
    cp_commit();

    int buf = 0;
    for (int c = 0; c < NCH; c++) {
        if (c + 1 < NCH) load_chunk(c + 1, buf ^ 1);
        cp_commit();
        cp_wait1();
        __syncthreads();

        const int l0 = c * CL;
#pragma unroll 8
        for (int li = 0; li < CL; li++) {
            float dt = sD[buf][li][hl];
            float xv = sX[buf][li][hl];
            float4 Bv = *reinterpret_cast<const float4*>(&sB[buf][li][s * 4]);
            float4 Cv = *reinterpret_cast<const float4*>(&sC[buf][li][s * 4]);
            float dx = dt * xv;

            float yv;
            hs[0] = fmaf(ex2_approx(dt * a2[0]), hs[0], dx * Bv.x); yv = hs[0] * Cv.x;
            hs[1] = fmaf(ex2_approx(dt * a2[1]), hs[1], dx * Bv.y); yv = fmaf(hs[1], Cv.y, yv);
            hs[2] = fmaf(ex2_approx(dt * a2[2]), hs[2], dx * Bv.z); yv = fmaf(hs[2], Cv.z, yv);
            hs[3] = fmaf(ex2_approx(dt * a2[3]), hs[3], dx * Bv.w); yv = fmaf(hs[3], Cv.w, yv);

            yv += __shfl_xor_sync(0xffffffffu, yv, 1);
            yv += __shfl_xor_sync(0xffffffffu, yv, 2);

            if (s == 0) {
                float yy = fmaf(Dv, xv, yv);
                __nv_bfloat16 hh = __float2bfloat16_rn(yy);
                size_t o = (size_t)(l0 + li) * HID + h;
                yh_b[o] = hh;
                yl_b[o] = __float2bfloat16_rn(yy - __bfloat162float(hh));
            }
        }
        __syncthreads();
        buf ^= 1;
    }
}

// ---------------------------------------------------------------------------
// launch
// ---------------------------------------------------------------------------
extern "C" void kernel_launch(void* const* d_in, const int* in_sizes, int n_in,
                              void* d_out, int out_size)
{
    const float* x     = (const float*)d_in[0];
    const float* Wx    = (const float*)d_in[1];
    const float* A_log = (const float*)d_in[2];
    const float* D     = (const float*)d_in[3];
    const float* Wout  = (const float*)d_in[4];
    float* out = (float*)d_out;

    __nv_bfloat16 *xhi, *xlo, *yhi, *ylo, *wdhi, *wdlo, *wohi, *wolo, *wbchi, *wbclo;
    float *dt_p, *bc_p;
    cudaGetSymbolAddress((void**)&xhi, g_xhi);
    cudaGetSymbolAddress((void**)&xlo, g_xlo);
    cudaGetSymbolAddress((void**)&yhi, g_yhi);
    cudaGetSymbolAddress((void**)&ylo, g_ylo);
    cudaGetSymbolAddress((void**)&wdhi, g_wdhi);
    cudaGetSymbolAddress((void**)&wdlo, g_wdlo);
    cudaGetSymbolAddress((void**)&wohi, g_wohi);
    cudaGetSymbolAddress((void**)&wolo, g_wolo);
    cudaGetSymbolAddress((void**)&wbchi, g_wbchi);
    cudaGetSymbolAddress((void**)&wbclo, g_wbclo);
    cudaGetSymbolAddress((void**)&dt_p, g_dt);
    cudaGetSymbolAddress((void**)&bc_p, g_bc);

    cudaFuncSetAttribute(gemm_bf16_mma, cudaFuncAttributeMaxDynamicSharedMemorySize, SMEM_TOTAL_G);

    // bf16 splits
    {
        int n4 = MROWS * HID / 4;
        split_bf16<<<(n4 + 255) / 256, 256>>>(x, xhi, xlo, n4);
        int w4 = HID * HID / 4;
        split_bf16<<<(w4 + 255) / 256, 256>>>(Wx + 2 * NST * HID, wdhi, wdlo, w4);
        split_bf16<<<(w4 + 255) / 256, 256>>>(Wout, wohi, wolo, w4);
        int bc4 = 2 * NST * HID / 4;
        split_bf16<<<(bc4 + 255) / 256, 256>>>(Wx, wbchi, wbclo, bc4);
    }

    // GEMM1 (tensor): dt = softplus(x @ Wdelta^T), bc = x @ Wbc^T (col block 8)
    gemm_bf16_mma<<<dim3(9, MROWS / 128), 512, SMEM_TOTAL_G>>>(
        xhi, xlo, wdhi, wdlo, wbchi, wbclo, dt_p, bc_p, 1);

    // selective scan (writes yhi/ylo directly)
    scan_kernel<<<BATCH * (HID / 32), 128>>>(dt_p, bc_p, x, A_log, D, yhi, ylo);

    // GEMM2 (tensor): out = y @ Wout^T
    gemm_bf16_mma<<<dim3(8, MROWS / 128), 512, SMEM_TOTAL_G>>>(
        yhi, ylo, wohi, wolo, nullptr, nullptr, out, nullptr, 0);
}

// round 8
// speedup vs baseline: 1.8691x; 1.0424x over previous
#include <cuda_runtime.h>
#include <cuda_bf16.h>
#include <cstdint>

// Problem constants
#define BATCH 4
#define L_SEQ 2048
#define HID   1024
#define NST   16
#define MROWS (BATCH * L_SEQ) // 8192

// ---------------------------------------------------------------------------
// Device-global scratch (zero-initialized; no allocation allowed)
// ---------------------------------------------------------------------------
__device__ __nv_bfloat16 g_xhi[(size_t)MROWS * HID];
__device__ __nv_bfloat16 g_xlo[(size_t)MROWS * HID];
__device__ __nv_bfloat16 g_yhi[(size_t)MROWS * HID];
__device__ __nv_bfloat16 g_ylo[(size_t)MROWS * HID];
__device__ __nv_bfloat16 g_wdhi[(size_t)HID * HID];    // Wx rows 32..1055 (delta)
__device__ __nv_bfloat16 g_wdlo[(size_t)HID * HID];
__device__ __nv_bfloat16 g_wohi[(size_t)HID * HID];    // Wout
__device__ __nv_bfloat16 g_wolo[(size_t)HID * HID];
__device__ __nv_bfloat16 g_wbchi[(size_t)128 * HID];   // Wx rows 0..31, zero-padded to 128
__device__ __nv_bfloat16 g_wbclo[(size_t)128 * HID];
__device__ float g_dt[(size_t)MROWS * HID];            // softplus(delta)
__device__ float g_bc[(size_t)MROWS * 2 * NST];        // B,C columns

// ---------------------------------------------------------------------------
// helpers
// ---------------------------------------------------------------------------
__device__ __forceinline__ uint32_t smem_u32(const void* p) {
    return (uint32_t)__cvta_generic_to_shared(p);
}
__device__ __forceinline__ void cp_async16(uint32_t dst, const void* src) {
    asm volatile("cp.async.cg.shared.global [%0], [%1], 16;\n" :: "r"(dst), "l"(src) : "memory");
}
__device__ __forceinline__ void cp_commit() {
    asm volatile("cp.async.commit_group;\n" ::: "memory");
}
__device__ __forceinline__ void cp_wait1() {
    asm volatile("cp.async.wait_group 1;\n" ::: "memory");
}
__device__ __forceinline__ float ex2_approx(float v) {
    float r;
    asm("ex2.approx.ftz.f32 %0, %1;" : "=f"(r) : "f"(v));
    return r;
}
__device__ __forceinline__ float softplus_f(float z) {
    return log1pf(expf(-fabsf(z))) + fmaxf(z, 0.0f);
}

// SW128 swizzle for 128-byte rows (TBK=64 bf16)
#define SWZ128(off) ((off) ^ (((off) >> 3) & 0x70))

#define LDSM_X4(r0, r1, r2, r3, addr) \
    asm volatile("ldmatrix.sync.aligned.m8n8.x4.shared.b16 {%0,%1,%2,%3}, [%4];" \
        : "=r"(r0), "=r"(r1), "=r"(r2), "=r"(r3) : "r"(addr))

#define MMA_BF16(c0, c1, c2, c3, a0, a1, a2, a3, b0, b1) \
    asm volatile("mma.sync.aligned.m16n8k16.row.col.f32.bf16.bf16.f32 " \
        "{%0,%1,%2,%3}, {%4,%5,%6,%7}, {%8,%9}, {%0,%1,%2,%3};" \
        : "+f"(c0), "+f"(c1), "+f"(c2), "+f"(c3) \
        : "r"(a0), "r"(a1), "r"(a2), "r"(a3), "r"(b0), "r"(b1))

// ---------------------------------------------------------------------------
// fp32 -> (bf16 hi, bf16 lo) split
// ---------------------------------------------------------------------------
__global__ __launch_bounds__(256) void split_bf16(
    const float* __restrict__ s, __nv_bfloat16* __restrict__ hi,
    __nv_bfloat16* __restrict__ lo, int n4)
{
    int i = blockIdx.x * blockDim.x + threadIdx.x;
    if (i >= n4) return;
    float4 v = reinterpret_cast<const float4*>(s)[i];
    __nv_bfloat16 h0 = __float2bfloat16_rn(v.x);
    __nv_bfloat16 h1 = __float2bfloat16_rn(v.y);
    __nv_bfloat16 h2 = __float2bfloat16_rn(v.z);
    __nv_bfloat16 h3 = __float2bfloat16_rn(v.w);
    __nv_bfloat16 l0 = __float2bfloat16_rn(v.x - __bfloat162float(h0));
    __nv_bfloat16 l1 = __float2bfloat16_rn(v.y - __bfloat162float(h1));
    __nv_bfloat16 l2 = __float2bfloat16_rn(v.z - __bfloat162float(h2));
    __nv_bfloat16 l3 = __float2bfloat16_rn(v.w - __bfloat162float(h3));
    __nv_bfloat162* H = reinterpret_cast<__nv_bfloat162*>(hi);
    __nv_bfloat162* L = reinterpret_cast<__nv_bfloat162*>(lo);
    __nv_bfloat162 a; a.x = h0; a.y = h1;
    __nv_bfloat162 b; b.x = h2; b.y = h3;
    __nv_bfloat162 c; c.x = l0; c.y = l1;
    __nv_bfloat162 d; d.x = l2; d.y = l3;
    H[2 * i] = a; H[2 * i + 1] = b;
    L[2 * i] = c; L[2 * i + 1] = d;
}

// ---------------------------------------------------------------------------
// bf16x3 GEMM via mma.sync (NT), fp32-accurate.
// CTA tile 128x128x64, 512 threads (16 warps, 4x4), warp tile 32x32.
// 3-stage cp.async pipeline (192 KB smem), SW128 rows, term-major MMA order.
// blockIdx.x == 8 (GEMM1 only): B/C projection against zero-padded Wbc.
// ---------------------------------------------------------------------------
#define TBK 64
#define NKS (HID / TBK)               // 16 K-stages
#define TILE_B (128 * 128)            // 16384 bytes per operand tile
#define STAGE_B (4 * TILE_B)          // 65536
#define NSTAGE 3
#define SMEM_TOTAL_G (NSTAGE * STAGE_B)  // 196608

__global__ __launch_bounds__(512) void gemm_bf16_mma(
    const __nv_bfloat16* __restrict__ Ahi, const __nv_bfloat16* __restrict__ Alo,
    const __nv_bfloat16* __restrict__ Bhi, const __nv_bfloat16* __restrict__ Blo,
    const __nv_bfloat16* __restrict__ BChi, const __nv_bfloat16* __restrict__ BClo,
    float* __restrict__ Out, float* __restrict__ OutBC, int do_softplus)
{
    extern __shared__ __align__(1024) uint8_t dsm[];
    const uint32_t sbase = smem_u32(dsm);
    const int t = threadIdx.x;
    const int lid = t & 31;
    const int wid = t >> 5;
    const int warpM = (wid >> 2) * 32;   // 0,32,64,96
    const int warpN = (wid & 3) * 32;    // 0,32,64,96
    const int bm = blockIdx.y * 128;
    const bool bc = (blockIdx.x == 8);
    const int bn = bc ? 0 : blockIdx.x * 128;

    const __nv_bfloat16* srcs[4];
    srcs[0] = Ahi + (size_t)bm * HID;
    srcs[1] = Alo + (size_t)bm * HID;
    srcs[2] = (bc ? BChi : Bhi + (size_t)bn * HID);
    srcs[3] = (bc ? BClo : Blo + (size_t)bn * HID);

    // stage loader: 4 tiles x (128 rows x 8 segs of 16B) = 4096 chunks / 512 thr
    auto load_stage = [&](int k0, uint32_t soff) {
#pragma unroll
        for (int tile = 0; tile < 4; tile++) {
            const __nv_bfloat16* sp = srcs[tile] + k0;
            uint32_t dbase = sbase + soff + tile * TILE_B;
#pragma unroll
            for (int i = 0; i < 2; i++) {
                int u = t + i * 512;           // 0..1023
                int row = u >> 3;
                int seg = u & 7;
                uint32_t off = SWZ128((uint32_t)(row * 128 + seg * 16));
                cp_async16(dbase + off, sp + (size_t)row * HID + seg * 8);
            }
        }
    };

    float acc[2][4][4];
#pragma unroll
    for (int i = 0; i < 2; i++)
#pragma unroll
        for (int j = 0; j < 4; j++)
#pragma unroll
            for (int q = 0; q < 4; q++) acc[i][j][q] = 0.0f;

    // lane addressing
    const int a_row = (lid & 15);
    const int a_khalf = (lid >> 4) << 4;
    const int b_q = lid >> 3;
    const int b_row = ((b_q >> 1) << 3) + (lid & 7);
    const int b_khalf = (b_q & 1) << 4;

    load_stage(0, 0);
    cp_commit();
    load_stage(TBK, STAGE_B);
    cp_commit();

    for (int k = 0; k < NKS; k++) {
        cp_wait1();              // stage k resident
        __syncthreads();         // everyone done with stage k-1
        if (k + 2 < NKS) load_stage((k + 2) * TBK, (uint32_t)((k + 2) % NSTAGE) * STAGE_B);
        cp_commit();

        const uint32_t sb = sbase + (uint32_t)(k % NSTAGE) * STAGE_B;
#pragma unroll
        for (int kk = 0; kk < 4; kk++) {
            uint32_t ah[8], al[8], bh[8], bl[8];
#pragma unroll
            for (int mt = 0; mt < 2; mt++) {
                uint32_t sw = SWZ128((uint32_t)((warpM + mt * 16 + a_row) * 128 + kk * 32 + a_khalf));
                LDSM_X4(ah[mt*4+0], ah[mt*4+1], ah[mt*4+2], ah[mt*4+3], sb + 0 * TILE_B + sw);
                LDSM_X4(al[mt*4+0], al[mt*4+1], al[mt*4+2], al[mt*4+3], sb + 1 * TILE_B + sw);
            }
#pragma unroll
            for (int g = 0; g < 2; g++) {
                uint32_t sw = SWZ128((uint32_t)((warpN + g * 16 + b_row) * 128 + kk * 32 + b_khalf));
                LDSM_X4(bh[g*4+0], bh[g*4+1], bh[g*4+2], bh[g*4+3], sb + 2 * TILE_B + sw);
                LDSM_X4(bl[g*4+0], bl[g*4+1], bl[g*4+2], bl[g*4+3], sb + 3 * TILE_B + sw);
            }
            // term-major: dependent MMAs on the same acc are 8 apart
#pragma unroll
            for (int mt = 0; mt < 2; mt++)
#pragma unroll
                for (int nt = 0; nt < 4; nt++) {
                    float* c = acc[mt][nt];
                    MMA_BF16(c[0], c[1], c[2], c[3],
                             ah[mt*4+0], ah[mt*4+1], ah[mt*4+2], ah[mt*4+3],
                             bh[nt*2+0], bh[nt*2+1]);
                }
#pragma unroll
            for (int mt = 0; mt < 2; mt++)
#pragma unroll
                for (int nt = 0; nt < 4; nt++) {
                    float* c = acc[mt][nt];
                    MMA_BF16(c[0], c[1], c[2], c[3],
                             ah[mt*4+0], ah[mt*4+1], ah[mt*4+2], ah[mt*4+3],
                             bl[nt*2+0], bl[nt*2+1]);
                }
#pragma unroll
            for (int mt = 0; mt < 2; mt++)
#pragma unroll
                for (int nt = 0; nt < 4; nt++) {
                    float* c = acc[mt][nt];
                    MMA_BF16(c[0], c[1], c[2], c[3],
                             al[mt*4+0], al[mt*4+1], al[mt*4+2], al[mt*4+3],
                             bh[nt*2+0], bh[nt*2+1]);
                }
        }
    }

    // epilogue
    const int tq = lid >> 2;
    const int tr = (lid & 3) * 2;
#pragma unroll
    for (int mt = 0; mt < 2; mt++) {
#pragma unroll
        for (int nt = 0; nt < 4; nt++) {
            float* c = acc[mt][nt];
            int mrow = bm + warpM + mt * 16 + tq;
            int ncol = warpN + nt * 8 + tr;
            if (!bc) {
                float v0 = c[0], v1 = c[1], v2 = c[2], v3 = c[3];
                if (do_softplus) {
                    v0 = softplus_f(v0); v1 = softplus_f(v1);
                    v2 = softplus_f(v2); v3 = softplus_f(v3);
                }
                *reinterpret_cast<float2*>(&Out[(size_t)mrow * HID + bn + ncol]) = make_float2(v0, v1);
                *reinterpret_cast<float2*>(&Out[(size_t)(mrow + 8) * HID + bn + ncol]) = make_float2(v2, v3);
            } else if (ncol < 2 * NST) {
                *reinterpret_cast<float2*>(&OutBC[(size_t)mrow * (2 * NST) + ncol]) = make_float2(c[0], c[1]);
                *reinterpret_cast<float2*>(&OutBC[(size_t)(mrow + 8) * (2 * NST) + ncol]) = make_float2(c[2], c[3]);
            }
        }
    }
}

// ---------------------------------------------------------------------------
// Selective scan; writes bf16 hi/lo directly (fused y split)
// ---------------------------------------------------------------------------
#define CL 32
#define NCH (L_SEQ / CL)

__global__ __launch_bounds__(128) void scan_kernel(
    const float* __restrict__ dt_g, const float* __restrict__ bc_g,
    const float* __restrict__ x, const float* __restrict__ A_log,
    const float* __restrict__ Dp,
    __nv_bfloat16* __restrict__ yhi, __nv_bfloat16* __restrict__ ylo)
{
    __shared__ __align__(16) float sD[2][CL][32];
    __shared__ __align__(16) float sX[2][CL][32];
    __shared__ __align__(16) float sB[2][CL][16];
    __shared__ __align__(16) float sC[2][CL][16];

    const int tid = threadIdx.x;
    const int b = blockIdx.x >> 5;
    const int hbase = (blockIdx.x & 31) * 32;
    const int lane = tid & 31;
    const int w = tid >> 5;
    const int s = lane & 3;
    const int hl = (w << 3) | (lane >> 2);
    const int h = hbase + hl;

    float a2[4], hs[4];
#pragma unroll
    for (int i = 0; i < 4; i++) {
        a2[i] = -expf(A_log[s * 4 + i]) * 1.4426950408889634f;
        hs[i] = 0.0f;
    }
    const float Dv = Dp[h];

    const float* dt_b = dt_g + (size_t)b * L_SEQ * HID;
    const float* bc_b = bc_g + (size_t)b * L_SEQ * 2 * NST;
    const float* x_b  = x    + (size_t)b * L_SEQ * HID;
    __nv_bfloat16* yh_b = yhi + (size_t)b * L_SEQ * HID;
    __nv_bfloat16* yl_b = ylo + (size_t)b * L_SEQ * HID;

    auto load_chunk = [&](int c, int buf) {
        const int l0 = c * CL;
#pragma unroll
        for (int r = 0; r < 2; r++) {
            int idx = tid + r * 128;
            int row = idx >> 3;
            int col = (idx & 7) * 4;
            cp_async16(smem_u32(&sD[buf][row][col]),
                       &dt_b[(size_t)(l0 + row) * HID + hbase + col]);
            cp_async16(smem_u32(&sX[buf][row][col]),
                       &x_b[(size_t)(l0 + row) * HID + hbase + col]);
        }
        {
            int row = tid >> 2;
            int col = (tid & 3) * 4;
            cp_async16(smem_u32(&sB[buf][row][col]),
                       &bc_b[(size_t)(l0 + row) * 2 * NST + col]);
            cp_async16(smem_u32(&sC[buf][row][col]),
                       &bc_b[(size_t)(l0 + row) * 2 * NST + NST + col]);
        }
    };

    load_chunk(0, 0);
    cp_commit();

    int buf = 0;
    for (int c = 0; c < NCH; c++) {
        if (c + 1 < NCH) load_chunk(c + 1, buf ^ 1);
        cp_commit();
        cp_wait1();
        __syncthreads();

        const int l0 = c * CL;
#pragma unroll 8
        for (int li = 0; li < CL; li++) {
            float dt = sD[buf][li][hl];
            float xv = sX[buf][li][hl];
            float4 Bv = *reinterpret_cast<const float4*>(&sB[buf][li][s * 4]);
            float4 Cv = *reinterpret_cast<const float4*>(&sC[buf][li][s * 4]);
            float dx = dt * xv;

            float yv;
            hs[0] = fmaf(ex2_approx(dt * a2[0]), hs[0], dx * Bv.x); yv = hs[0] * Cv.x;
            hs[1] = fmaf(ex2_approx(dt * a2[1]), hs[1], dx * Bv.y); yv = fmaf(hs[1], Cv.y, yv);
            hs[2] = fmaf(ex2_approx(dt * a2[2]), hs[2], dx * Bv.z); yv = fmaf(hs[2], Cv.z, yv);
            hs[3] = fmaf(ex2_approx(dt * a2[3]), hs[3], dx * Bv.w); yv = fmaf(hs[3], Cv.w, yv);

            yv += __shfl_xor_sync(0xffffffffu, yv, 1);
            yv += __shfl_xor_sync(0xffffffffu, yv, 2);

            if (s == 0) {
                float yy = fmaf(Dv, xv, yv);
                __nv_bfloat16 hh = __float2bfloat16_rn(yy);
                size_t o = (size_t)(l0 + li) * HID + h;
                yh_b[o] = hh;
                yl_b[o] = __float2bfloat16_rn(yy - __bfloat162float(hh));
            }
        }
        __syncthreads();
        buf ^= 1;
    }
}

// ---------------------------------------------------------------------------
// launch
// ---------------------------------------------------------------------------
extern "C" void kernel_launch(void* const* d_in, const int* in_sizes, int n_in,
                              void* d_out, int out_size)
{
    const float* x     = (const float*)d_in[0];
    const float* Wx    = (const float*)d_in[1];
    const float* A_log = (const float*)d_in[2];
    const float* D     = (const float*)d_in[3];
    const float* Wout  = (const float*)d_in[4];
    float* out = (float*)d_out;

    __nv_bfloat16 *xhi, *xlo, *yhi, *ylo, *wdhi, *wdlo, *wohi, *wolo, *wbchi, *wbclo;
    float *dt_p, *bc_p;
    cudaGetSymbolAddress((void**)&xhi, g_xhi);
    cudaGetSymbolAddress((void**)&xlo, g_xlo);
    cudaGetSymbolAddress((void**)&yhi, g_yhi);
    cudaGetSymbolAddress((void**)&ylo, g_ylo);
    cudaGetSymbolAddress((void**)&wdhi, g_wdhi);
    cudaGetSymbolAddress((void**)&wdlo, g_wdlo);
    cudaGetSymbolAddress((void**)&wohi, g_wohi);
    cudaGetSymbolAddress((void**)&wolo, g_wolo);
    cudaGetSymbolAddress((void**)&wbchi, g_wbchi);
    cudaGetSymbolAddress((void**)&wbclo, g_wbclo);
    cudaGetSymbolAddress((void**)&dt_p, g_dt);
    cudaGetSymbolAddress((void**)&bc_p, g_bc);

    cudaFuncSetAttribute(gemm_bf16_mma, cudaFuncAttributeMaxDynamicSharedMemorySize, SMEM_TOTAL_G);

    // bf16 splits
    {
        int n4 = MROWS * HID / 4;
        split_bf16<<<(n4 + 255) / 256, 256>>>(x, xhi, xlo, n4);
        int w4 = HID * HID / 4;
        split_bf16<<<(w4 + 255) / 256, 256>>>(Wx + 2 * NST * HID, wdhi, wdlo, w4);
        split_bf16<<<(w4 + 255) / 256, 256>>>(Wout, wohi, wolo, w4);
        int bc4 = 2 * NST * HID / 4;
        split_bf16<<<(bc4 + 255) / 256, 256>>>(Wx, wbchi, wbclo, bc4);
    }

    // GEMM1 (tensor): dt = softplus(x @ Wdelta^T), bc = x @ Wbc^T (col block 8)
    gemm_bf16_mma<<<dim3(9, MROWS / 128), 512, SMEM_TOTAL_G>>>(
        xhi, xlo, wdhi, wdlo, wbchi, wbclo, dt_p, bc_p, 1);

    // selective scan (writes yhi/ylo directly)
    scan_kernel<<<BATCH * (HID / 32), 128>>>(dt_p, bc_p, x, A_log, D, yhi, ylo);

    // GEMM2 (tensor): out = y @ Wout^T
    gemm_bf16_mma<<<dim3(8, MROWS / 128), 512, SMEM_TOTAL_G>>>(
        yhi, ylo, wohi, wolo, nullptr, nullptr, out, nullptr, 0);
}

// round 10
// speedup vs baseline: 2.0291x; 1.0856x over previous
#include <cuda_runtime.h>
#include <cuda_bf16.h>
#include <cstdint>

// Problem constants
#define BATCH 4
#define L_SEQ 2048
#define HID   1024
#define NST   16
#define MROWS (BATCH * L_SEQ) // 8192

// ---------------------------------------------------------------------------
// Device-global scratch (zero-initialized; no allocation allowed)
// ---------------------------------------------------------------------------
__device__ __nv_bfloat16 g_xhi[(size_t)MROWS * HID];
__device__ __nv_bfloat16 g_xlo[(size_t)MROWS * HID];
__device__ __nv_bfloat16 g_yhi[(size_t)MROWS * HID];
__device__ __nv_bfloat16 g_ylo[(size_t)MROWS * HID];
__device__ __nv_bfloat16 g_wdhi[(size_t)HID * HID];    // Wx rows 32..1055 (delta)
__device__ __nv_bfloat16 g_wdlo[(size_t)HID * HID];
__device__ __nv_bfloat16 g_wohi[(size_t)HID * HID];    // Wout
__device__ __nv_bfloat16 g_wolo[(size_t)HID * HID];
__device__ __nv_bfloat16 g_wbchi[(size_t)128 * HID];   // Wx rows 0..31, zero-padded to 128
__device__ __nv_bfloat16 g_wbclo[(size_t)128 * HID];
__device__ float g_dt[(size_t)MROWS * HID];            // softplus(delta)
__device__ float g_bc[(size_t)MROWS * 2 * NST];        // B,C columns

// ---------------------------------------------------------------------------
// helpers
// ---------------------------------------------------------------------------
__device__ __forceinline__ uint32_t smem_u32(const void* p) {
    return (uint32_t)__cvta_generic_to_shared(p);
}
__device__ __forceinline__ void cp_async16(uint32_t dst, const void* src) {
    asm volatile("cp.async.cg.shared.global [%0], [%1], 16;\n" :: "r"(dst), "l"(src) : "memory");
}
__device__ __forceinline__ void cp_commit() {
    asm volatile("cp.async.commit_group;\n" ::: "memory");
}
__device__ __forceinline__ void cp_wait1() {
    asm volatile("cp.async.wait_group 1;\n" ::: "memory");
}
__device__ __forceinline__ float ex2_approx(float v) {
    float r;
    asm("ex2.approx.ftz.f32 %0, %1;" : "=f"(r) : "f"(v));
    return r;
}
__device__ __forceinline__ float softplus_f(float z) {
    return log1pf(expf(-fabsf(z))) + fmaxf(z, 0.0f);
}

// SW128 swizzle for 128-byte rows (TBK=64 bf16)
#define SWZ128(off) ((off) ^ (((off) >> 3) & 0x70))

#define LDSM_X4(r0, r1, r2, r3, addr) \
    asm volatile("ldmatrix.sync.aligned.m8n8.x4.shared.b16 {%0,%1,%2,%3}, [%4];" \
        : "=r"(r0), "=r"(r1), "=r"(r2), "=r"(r3) : "r"(addr))

#define MMA_BF16(c0, c1, c2, c3, a0, a1, a2, a3, b0, b1) \
    asm volatile("mma.sync.aligned.m16n8k16.row.col.f32.bf16.bf16.f32 " \
        "{%0,%1,%2,%3}, {%4,%5,%6,%7}, {%8,%9}, {%0,%1,%2,%3};" \
        : "+f"(c0), "+f"(c1), "+f"(c2), "+f"(c3) \
        : "r"(a0), "r"(a1), "r"(a2), "r"(a3), "r"(b0), "r"(b1))

// ---------------------------------------------------------------------------
// fp32 -> (bf16 hi, bf16 lo) split
// ---------------------------------------------------------------------------
__global__ __launch_bounds__(256) void split_bf16(
    const float* __restrict__ s, __nv_bfloat16* __restrict__ hi,
    __nv_bfloat16* __restrict__ lo, int n4)
{
    int i = blockIdx.x * blockDim.x + threadIdx.x;
    if (i >= n4) return;
    float4 v = reinterpret_cast<const float4*>(s)[i];
    __nv_bfloat16 h0 = __float2bfloat16_rn(v.x);
    __nv_bfloat16 h1 = __float2bfloat16_rn(v.y);
    __nv_bfloat16 h2 = __float2bfloat16_rn(v.z);
    __nv_bfloat16 h3 = __float2bfloat16_rn(v.w);
    __nv_bfloat16 l0 = __float2bfloat16_rn(v.x - __bfloat162float(h0));
    __nv_bfloat16 l1 = __float2bfloat16_rn(v.y - __bfloat162float(h1));
    __nv_bfloat16 l2 = __float2bfloat16_rn(v.z - __bfloat162float(h2));
    __nv_bfloat16 l3 = __float2bfloat16_rn(v.w - __bfloat162float(h3));
    __nv_bfloat162* H = reinterpret_cast<__nv_bfloat162*>(hi);
    __nv_bfloat162* L = reinterpret_cast<__nv_bfloat162*>(lo);
    __nv_bfloat162 a; a.x = h0; a.y = h1;
    __nv_bfloat162 b; b.x = h2; b.y = h3;
    __nv_bfloat162 c; c.x = l0; c.y = l1;
    __nv_bfloat162 d; d.x = l2; d.y = l3;
    H[2 * i] = a; H[2 * i + 1] = b;
    L[2 * i] = c; L[2 * i + 1] = d;
}

// ---------------------------------------------------------------------------
// bf16x3 GEMM via mma.sync (NT), fp32-accurate.
// CTA tile 64x128x64, 256 threads (8 warps, 2x4), warp tile 32x32.
// 2-stage cp.async pipeline, 48 KB/stage -> 96 KB smem -> 2 CTAs/SM.
// blockIdx.x == 8 (GEMM1 only): B/C projection against zero-padded Wbc.
// ---------------------------------------------------------------------------
#define TBK 64
#define NKS (HID / TBK)               // 16 K-stages
#define A_TILE_B (64 * 128)           // 8192 bytes (64 rows x 128B)
#define B_TILE_B (128 * 128)          // 16384 bytes
#define OFF_AHI 0
#define OFF_ALO (A_TILE_B)
#define OFF_BHI (2 * A_TILE_B)
#define OFF_BLO (2 * A_TILE_B + B_TILE_B)
#define STAGE_B (2 * A_TILE_B + 2 * B_TILE_B)   // 49152
#define SMEM_TOTAL_G (2 * STAGE_B)              // 98304

__global__ __launch_bounds__(256, 2) void gemm_bf16_mma(
    const __nv_bfloat16* __restrict__ Ahi, const __nv_bfloat16* __restrict__ Alo,
    const __nv_bfloat16* __restrict__ Bhi, const __nv_bfloat16* __restrict__ Blo,
    const __nv_bfloat16* __restrict__ BChi, const __nv_bfloat16* __restrict__ BClo,
    float* __restrict__ Out, float* __restrict__ OutBC, int do_softplus)
{
    extern __shared__ __align__(1024) uint8_t dsm[];
    const uint32_t sbase = smem_u32(dsm);
    const int t = threadIdx.x;
    const int lid = t & 31;
    const int wid = t >> 5;
    const int warpM = (wid >> 2) * 32;   // 0,32
    const int warpN = (wid & 3) * 32;    // 0..96
    const int bm = blockIdx.y * 64;
    const bool bc = (blockIdx.x == 8);
    const int bn = bc ? 0 : blockIdx.x * 128;

    const __nv_bfloat16* aSrcs[2] = { Ahi + (size_t)bm * HID, Alo + (size_t)bm * HID };
    const __nv_bfloat16* bSrcs[2] = {
        (bc ? BChi : Bhi + (size_t)bn * HID),
        (bc ? BClo : Blo + (size_t)bn * HID) };

    // stage loader (256 threads): A tiles 512 chunks each, B tiles 1024 each
    auto load_stage = [&](int k0, uint32_t soff) {
#pragma unroll
        for (int h = 0; h < 2; h++) {
            uint32_t dbase = sbase + soff + (h ? OFF_ALO : OFF_AHI);
            const __nv_bfloat16* sp = aSrcs[h] + k0;
#pragma unroll
            for (int i = 0; i < 2; i++) {
                int u = t + i * 256;          // 0..511
                int row = u >> 3;             // 0..63
                int seg = u & 7;
                uint32_t off = SWZ128((uint32_t)(row * 128 + seg * 16));
                cp_async16(dbase + off, sp + (size_t)row * HID + seg * 8);
            }
        }
#pragma unroll
        for (int h = 0; h < 2; h++) {
            uint32_t dbase = sbase + soff + (h ? OFF_BLO : OFF_BHI);
            const __nv_bfloat16* sp = bSrcs[h] + k0;
#pragma unroll
            for (int i = 0; i < 4; i++) {
                int u = t + i * 256;          // 0..1023
                int row = u >> 3;             // 0..127
                int seg = u & 7;
                uint32_t off = SWZ128((uint32_t)(row * 128 + seg * 16));
                cp_async16(dbase + off, sp + (size_t)row * HID + seg * 8);
            }
        }
    };

    float acc[2][4][4];
#pragma unroll
    for (int i = 0; i < 2; i++)
#pragma unroll
        for (int j = 0; j < 4; j++)
#pragma unroll
            for (int q = 0; q < 4; q++) acc[i][j][q] = 0.0f;

    // lane addressing
    const int a_row = (lid & 15);
    const int a_khalf = (lid >> 4) << 4;
    const int b_q = lid >> 3;
    const int b_row = ((b_q >> 1) << 3) + (lid & 7);
    const int b_khalf = (b_q & 1) << 4;

    load_stage(0, 0);
    cp_commit();
    load_stage(TBK, STAGE_B);
    cp_commit();

    for (int k = 0; k < NKS; k++) {
        cp_wait1();              // stage k's group complete (k+1 may pend)
        __syncthreads();         // data visible to all warps

        const uint32_t sb = sbase + (uint32_t)(k & 1) * STAGE_B;
#pragma unroll
        for (int kk = 0; kk < 4; kk++) {
            uint32_t ah[8], al[8], bh[8], bl[8];
#pragma unroll
            for (int mt = 0; mt < 2; mt++) {
                uint32_t sw = SWZ128((uint32_t)((warpM + mt * 16 + a_row) * 128 + kk * 32 + a_khalf));
                LDSM_X4(ah[mt*4+0], ah[mt*4+1], ah[mt*4+2], ah[mt*4+3], sb + OFF_AHI + sw);
                LDSM_X4(al[mt*4+0], al[mt*4+1], al[mt*4+2], al[mt*4+3], sb + OFF_ALO + sw);
            }
#pragma unroll
            for (int g = 0; g < 2; g++) {
                uint32_t sw = SWZ128((uint32_t)((warpN + g * 16 + b_row) * 128 + kk * 32 + b_khalf));
                LDSM_X4(bh[g*4+0], bh[g*4+1], bh[g*4+2], bh[g*4+3], sb + OFF_BHI + sw);
                LDSM_X4(bl[g*4+0], bl[g*4+1], bl[g*4+2], bl[g*4+3], sb + OFF_BLO + sw);
            }
            // term-major: dependent MMAs on the same acc are 8 apart
#pragma unroll
            for (int mt = 0; mt < 2; mt++)
#pragma unroll
                for (int nt = 0; nt < 4; nt++) {
                    float* c = acc[mt][nt];
                    MMA_BF16(c[0], c[1], c[2], c[3],
                             ah[mt*4+0], ah[mt*4+1], ah[mt*4+2], ah[mt*4+3],
                             bh[nt*2+0], bh[nt*2+1]);
                }
#pragma unroll
            for (int mt = 0; mt < 2; mt++)
#pragma unroll
                for (int nt = 0; nt < 4; nt++) {
                    float* c = acc[mt][nt];
                    MMA_BF16(c[0], c[1], c[2], c[3],
                             ah[mt*4+0], ah[mt*4+1], ah[mt*4+2], ah[mt*4+3],
                             bl[nt*2+0], bl[nt*2+1]);
                }
#pragma unroll
            for (int mt = 0; mt < 2; mt++)
#pragma unroll
                for (int nt = 0; nt < 4; nt++) {
                    float* c = acc[mt][nt];
                    MMA_BF16(c[0], c[1], c[2], c[3],
                             al[mt*4+0], al[mt*4+1], al[mt*4+2], al[mt*4+3],
                             bh[nt*2+0], bh[nt*2+1]);
                }
        }

        __syncthreads();         // all warps done with buffer k&1
        if (k + 2 < NKS) load_stage((k + 2) * TBK, (uint32_t)(k & 1) * STAGE_B);
        cp_commit();             // unconditional: keeps wait_group accounting exact
    }

    // epilogue
    const int tq = lid >> 2;
    const int tr = (lid & 3) * 2;
#pragma unroll
    for (int mt = 0; mt < 2; mt++) {
#pragma unroll
        for (int nt = 0; nt < 4; nt++) {
            float* c = acc[mt][nt];
            int mrow = bm + warpM + mt * 16 + tq;
            int ncol = warpN + nt * 8 + tr;
            if (!bc) {
                float v0 = c[0], v1 = c[1], v2 = c[2], v3 = c[3];
                if (do_softplus) {
                    v0 = softplus_f(v0); v1 = softplus_f(v1);
                    v2 = softplus_f(v2); v3 = softplus_f(v3);
                }
                *reinterpret_cast<float2*>(&Out[(size_t)mrow * HID + bn + ncol]) = make_float2(v0, v1);
                *reinterpret_cast<float2*>(&Out[(size_t)(mrow + 8) * HID + bn + ncol]) = make_float2(v2, v3);
            } else if (ncol < 2 * NST) {
                *reinterpret_cast<float2*>(&OutBC[(size_t)mrow * (2 * NST) + ncol]) = make_float2(c[0], c[1]);
                *reinterpret_cast<float2*>(&OutBC[(size_t)(mrow + 8) * (2 * NST) + ncol]) = make_float2(c[2], c[3]);
            }
        }
    }
}

// ---------------------------------------------------------------------------
// Selective scan; writes bf16 hi/lo directly (fused y split)
// ---------------------------------------------------------------------------
#define CL 32
#define NCH (L_SEQ / CL)

__global__ __launch_bounds__(128) void scan_kernel(
    const float* __restrict__ dt_g, const float* __restrict__ bc_g,
    const float* __restrict__ x, const float* __restrict__ A_log,
    const float* __restrict__ Dp,
    __nv_bfloat16* __restrict__ yhi, __nv_bfloat16* __restrict__ ylo)
{
    __shared__ __align__(16) float sD[2][CL][32];
    __shared__ __align__(16) float sX[2][CL][32];
    __shared__ __align__(16) float sB[2][CL][16];
    __shared__ __align__(16) float sC[2][CL][16];

    const int tid = threadIdx.x;
    const int b = blockIdx.x >> 5;
    const int hbase = (blockIdx.x & 31) * 32;
    const int lane = tid & 31;
    const int w = tid >> 5;
    const int s = lane & 3;
    const int hl = (w << 3) | (lane >> 2);
    const int h = hbase + hl;

    float a2[4], hs[4];
#pragma unroll
    for (int i = 0; i < 4; i++) {
        a2[i] = -expf(A_log[s * 4 + i]) * 1.4426950408889634f;
        hs[i] = 0.0f;
    }
    const float Dv = Dp[h];

    const float* dt_b = dt_g + (size_t)b * L_SEQ * HID;
    const float* bc_b = bc_g + (size_t)b * L_SEQ * 2 * NST;
    const float* x_b  = x    + (size_t)b * L_SEQ * HID;
    __nv_bfloat16* yh_b = yhi + (size_t)b * L_SEQ * HID;
    __nv_bfloat16* yl_b = ylo + (size_t)b * L_SEQ * HID;

    auto load_chunk = [&](int c, int buf) {
        const int l0 = c * CL;
#pragma unroll
        for (int r = 0; r < 2; r++) {
            int idx = tid + r * 128;
            int row = idx >> 3;
            int col = (idx & 7) * 4;
            cp_async16(smem_u32(&sD[buf][row][col]),
                       &dt_b[(size_t)(l0 + row) * HID + hbase + col]);
            cp_async16(smem_u32(&sX[buf][row][col]),
                       &x_b[(size_t)(l0 + row) * HID + hbase + col]);
        }
        {
            int row = tid >> 2;
            int col = (tid & 3) * 4;
            cp_async16(smem_u32(&sB[buf][row][col]),
                       &bc_b[(size_t)(l0 + row) * 2 * NST + col]);
            cp_async16(smem_u32(&sC[buf][row][col]),
                       &bc_b[(size_t)(l0 + row) * 2 * NST + NST + col]);
        }
    };

    load_chunk(0, 0);
    cp_commit();

    int buf = 0;
    for (int c = 0; c < NCH; c++) {
        if (c + 1 < NCH) load_chunk(c + 1, buf ^ 1);
        cp_commit();
        cp_wait1();
        __syncthreads();

        const int l0 = c * CL;
#pragma unroll 8
        for (int li = 0; li < CL; li++) {
            float dt = sD[buf][li][hl];
            float xv = sX[buf][li][hl];
            float4 Bv = *reinterpret_cast<const float4*>(&sB[buf][li][s * 4]);
            float4 Cv = *reinterpret_cast<const float4*>(&sC[buf][li][s * 4]);
            float dx = dt * xv;

            float yv;
            hs[0] = fmaf(ex2_approx(dt * a2[0]), hs[0], dx * Bv.x); yv = hs[0] * Cv.x;
            hs[1] = fmaf(ex2_approx(dt * a2[1]), hs[1], dx * Bv.y); yv = fmaf(hs[1], Cv.y, yv);
            hs[2] = fmaf(ex2_approx(dt * a2[2]), hs[2], dx * Bv.z); yv = fmaf(hs[2], Cv.z, yv);
            hs[3] = fmaf(ex2_approx(dt * a2[3]), hs[3], dx * Bv.w); yv = fmaf(hs[3], Cv.w, yv);

            yv += __shfl_xor_sync(0xffffffffu, yv, 1);
            yv += __shfl_xor_sync(0xffffffffu, yv, 2);

            if (s == 0) {
                float yy = fmaf(Dv, xv, yv);
                __nv_bfloat16 hh = __float2bfloat16_rn(yy);
                size_t o = (size_t)(l0 + li) * HID + h;
                yh_b[o] = hh;
                yl_b[o] = __float2bfloat16_rn(yy - __bfloat162float(hh));
            }
        }
        __syncthreads();
        buf ^= 1;
    }
}

// ---------------------------------------------------------------------------
// launch
// ---------------------------------------------------------------------------
extern "C" void kernel_launch(void* const* d_in, const int* in_sizes, int n_in,
                              void* d_out, int out_size)
{
    const float* x     = (const float*)d_in[0];
    const float* Wx    = (const float*)d_in[1];
    const float* A_log = (const float*)d_in[2];
    const float* D     = (const float*)d_in[3];
    const float* Wout  = (const float*)d_in[4];
    float* out = (float*)d_out;

    __nv_bfloat16 *xhi, *xlo, *yhi, *ylo, *wdhi, *wdlo, *wohi, *wolo, *wbchi, *wbclo;
    float *dt_p, *bc_p;
    cudaGetSymbolAddress((void**)&xhi, g_xhi);
    cudaGetSymbolAddress((void**)&xlo, g_xlo);
    cudaGetSymbolAddress((void**)&yhi, g_yhi);
    cudaGetSymbolAddress((void**)&ylo, g_ylo);
    cudaGetSymbolAddress((void**)&wdhi, g_wdhi);
    cudaGetSymbolAddress((void**)&wdlo, g_wdlo);
    cudaGetSymbolAddress((void**)&wohi, g_wohi);
    cudaGetSymbolAddress((void**)&wolo, g_wolo);
    cudaGetSymbolAddress((void**)&wbchi, g_wbchi);
    cudaGetSymbolAddress((void**)&wbclo, g_wbclo);
    cudaGetSymbolAddress((void**)&dt_p, g_dt);
    cudaGetSymbolAddress((void**)&bc_p, g_bc);

    cudaFuncSetAttribute(gemm_bf16_mma, cudaFuncAttributeMaxDynamicSharedMemorySize, SMEM_TOTAL_G);

    // bf16 splits
    {
        int n4 = MROWS * HID / 4;
        split_bf16<<<(n4 + 255) / 256, 256>>>(x, xhi, xlo, n4);
        int w4 = HID * HID / 4;
        split_bf16<<<(w4 + 255) / 256, 256>>>(Wx + 2 * NST * HID, wdhi, wdlo, w4);
        split_bf16<<<(w4 + 255) / 256, 256>>>(Wout, wohi, wolo, w4);
        int bc4 = 2 * NST * HID / 4;
        split_bf16<<<(bc4 + 255) / 256, 256>>>(Wx, wbchi, wbclo, bc4);
    }

    // GEMM1 (tensor): dt = softplus(x @ Wdelta^T), bc = x @ Wbc^T (col block 8)
    gemm_bf16_mma<<<dim3(9, MROWS / 64), 256, SMEM_TOTAL_G>>>(
        xhi, xlo, wdhi, wdlo, wbchi, wbclo, dt_p, bc_p, 1);

    // selective scan (writes yhi/ylo directly)
    scan_kernel<<<BATCH * (HID / 32), 128>>>(dt_p, bc_p, x, A_log, D, yhi, ylo);

    // GEMM2 (tensor): out = y @ Wout^T
    gemm_bf16_mma<<<dim3(8, MROWS / 64), 256, SMEM_TOTAL_G>>>(
        yhi, ylo, wohi, wolo, nullptr, nullptr, out, nullptr, 0);
}

// round 12
// speedup vs baseline: 3.1507x; 1.5528x over previous
#include <cuda_runtime.h>
#include <cuda_fp16.h>
#include <cstdint>

// Problem constants
#define BATCH 4
#define L_SEQ 2048
#define HID   1024
#define NST   16
#define MROWS (BATCH * L_SEQ) // 8192

// ---------------------------------------------------------------------------
// Device-global scratch (zero-initialized; no allocation allowed)
// ---------------------------------------------------------------------------
__device__ __half g_xh [(size_t)MROWS * HID];     // x in fp16 (unsplit A)
__device__ __half g_yh [(size_t)MROWS * HID];     // scan output in fp16 (unsplit A)
__device__ __half g_wdhi[(size_t)HID * HID];      // Wx rows 32..1055 (delta), fp16 hi
__device__ __half g_wdlo[(size_t)HID * HID];      //                      fp16 lo
__device__ __half g_wohi[(size_t)HID * HID];      // Wout hi
__device__ __half g_wolo[(size_t)HID * HID];      // Wout lo
__device__ __half g_wbchi[(size_t)128 * HID];     // Wx rows 0..31 zero-padded, hi
__device__ __half g_wbclo[(size_t)128 * HID];     //                            lo
__device__ float g_dt[(size_t)MROWS * HID];       // softplus(delta)
__device__ float g_bc[(size_t)MROWS * 2 * NST];   // B,C columns

// ---------------------------------------------------------------------------
// helpers
// ---------------------------------------------------------------------------
__device__ __forceinline__ uint32_t smem_u32(const void* p) {
    return (uint32_t)__cvta_generic_to_shared(p);
}
__device__ __forceinline__ void cp_async16(uint32_t dst, const void* src) {
    asm volatile("cp.async.cg.shared.global [%0], [%1], 16;\n" :: "r"(dst), "l"(src) : "memory");
}
__device__ __forceinline__ void cp_commit() {
    asm volatile("cp.async.commit_group;\n" ::: "memory");
}
__device__ __forceinline__ void cp_wait1() {
    asm volatile("cp.async.wait_group 1;\n" ::: "memory");
}
__device__ __forceinline__ float ex2_approx(float v) {
    float r;
    asm("ex2.approx.ftz.f32 %0, %1;" : "=f"(r) : "f"(v));
    return r;
}
__device__ __forceinline__ float softplus_f(float z) {
    return log1pf(expf(-fabsf(z))) + fmaxf(z, 0.0f);
}

// SW128 swizzle for 128-byte rows (TBK=64 fp16)
#define SWZ128(off) ((off) ^ (((off) >> 3) & 0x70))

#define LDSM_X4(r0, r1, r2, r3, addr) \
    asm volatile("ldmatrix.sync.aligned.m8n8.x4.shared.b16 {%0,%1,%2,%3}, [%4];" \
        : "=r"(r0), "=r"(r1), "=r"(r2), "=r"(r3) : "r"(addr))

#define MMA_FP16(c0, c1, c2, c3, a0, a1, a2, a3, b0, b1) \
    asm volatile("mma.sync.aligned.m16n8k16.row.col.f32.f16.f16.f32 " \
        "{%0,%1,%2,%3}, {%4,%5,%6,%7}, {%8,%9}, {%0,%1,%2,%3};" \
        : "+f"(c0), "+f"(c1), "+f"(c2), "+f"(c3) \
        : "r"(a0), "r"(a1), "r"(a2), "r"(a3), "r"(b0), "r"(b1))

// ---------------------------------------------------------------------------
// fp32 -> fp16 convert (A operands)
// ---------------------------------------------------------------------------
__global__ __launch_bounds__(256) void conv_fp16(
    const float* __restrict__ s, __half* __restrict__ d, int n4)
{
    int i = blockIdx.x * blockDim.x + threadIdx.x;
    if (i >= n4) return;
    float4 v = reinterpret_cast<const float4*>(s)[i];
    __half2* D = reinterpret_cast<__half2*>(d);
    D[2 * i]     = __floats2half2_rn(v.x, v.y);
    D[2 * i + 1] = __floats2half2_rn(v.z, v.w);
}

// ---------------------------------------------------------------------------
// fp32 -> (fp16 hi, fp16 lo) split (B operands / weights)
// ---------------------------------------------------------------------------
__global__ __launch_bounds__(256) void split_fp16(
    const float* __restrict__ s, __half* __restrict__ hi,
    __half* __restrict__ lo, int n4)
{
    int i = blockIdx.x * blockDim.x + threadIdx.x;
    if (i >= n4) return;
    float4 v = reinterpret_cast<const float4*>(s)[i];
    float h0 = __half2float(__float2half_rn(v.x));
    float h1 = __half2float(__float2half_rn(v.y));
    float h2 = __half2float(__float2half_rn(v.z));
    float h3 = __half2float(__float2half_rn(v.w));
    __half2* H = reinterpret_cast<__half2*>(hi);
    __half2* L = reinterpret_cast<__half2*>(lo);
    H[2 * i]     = __floats2half2_rn(h0, h1);
    H[2 * i + 1] = __floats2half2_rn(h2, h3);
    L[2 * i]     = __floats2half2_rn(v.x - h0, v.y - h1);
    L[2 * i + 1] = __floats2half2_rn(v.z - h2, v.w - h3);
}

// ---------------------------------------------------------------------------
// fp16 2-term GEMM via mma.sync (NT): Out = A * (Bhi + Blo)^T, ~2e-4 accuracy.
// CTA tile 128x128x64, 256 threads (8 warps, 2x4), warp tile 64x32.
// 2-stage cp.async pipeline, 48 KB/stage -> 96 KB smem -> 2 CTAs/SM.
// blockIdx.x == 8 (GEMM1 only): B/C projection against zero-padded Wbc.
// ---------------------------------------------------------------------------
#define TBK 64
#define NKS (HID / TBK)               // 16 K-stages
#define T128_B (128 * 128)            // 16384 bytes (128 rows x 128B)
#define OFF_A  0
#define OFF_BH (T128_B)
#define OFF_BL (2 * T128_B)
#define STAGE_B (3 * T128_B)          // 49152
#define SMEM_TOTAL_G (2 * STAGE_B)    // 98304

__global__ __launch_bounds__(256, 2) void gemm_fp16_mma(
    const __half* __restrict__ A,
    const __half* __restrict__ Bhi, const __half* __restrict__ Blo,
    const __half* __restrict__ BChi, const __half* __restrict__ BClo,
    float* __restrict__ Out, float* __restrict__ OutBC, int do_softplus)
{
    extern __shared__ __align__(1024) uint8_t dsm[];
    const uint32_t sbase = smem_u32(dsm);
    const int t = threadIdx.x;
    const int lid = t & 31;
    const int wid = t >> 5;
    const int warpM = (wid >> 2) * 64;   // 0,64
    const int warpN = (wid & 3) * 32;    // 0..96
    const int bm = blockIdx.y * 128;
    const bool bc = (blockIdx.x == 8);
    const int bn = bc ? 0 : blockIdx.x * 128;

    const __half* srcs[3];
    srcs[0] = A + (size_t)bm * HID;
    srcs[1] = (bc ? BChi : Bhi + (size_t)bn * HID);
    srcs[2] = (bc ? BClo : Blo + (size_t)bn * HID);

    // stage loader: 3 tiles x (128 rows x 8 segs of 16B) = 3072 chunks / 256 thr
    auto load_stage = [&](int k0, uint32_t soff) {
#pragma unroll
        for (int tile = 0; tile < 3; tile++) {
            const __half* sp = srcs[tile] + k0;
            uint32_t dbase = sbase + soff + tile * T128_B;
#pragma unroll
            for (int i = 0; i < 4; i++) {
                int u = t + i * 256;          // 0..1023
                int row = u >> 3;             // 0..127
                int seg = u & 7;
                uint32_t off = SWZ128((uint32_t)(row * 128 + seg * 16));
                cp_async16(dbase + off, sp + (size_t)row * HID + seg * 8);
            }
        }
    };

    float acc[4][4][4];
#pragma unroll
    for (int i = 0; i < 4; i++)
#pragma unroll
        for (int j = 0; j < 4; j++)
#pragma unroll
            for (int q = 0; q < 4; q++) acc[i][j][q] = 0.0f;

    // lane addressing
    const int a_row = (lid & 15);
    const int a_khalf = (lid >> 4) << 4;
    const int b_q = lid >> 3;
    const int b_row = ((b_q >> 1) << 3) + (lid & 7);
    const int b_khalf = (b_q & 1) << 4;

    load_stage(0, 0);
    cp_commit();
    load_stage(TBK, STAGE_B);
    cp_commit();

    for (int k = 0; k < NKS; k++) {
        cp_wait1();              // stage k's group complete (k+1 may pend)
        __syncthreads();         // data visible to all warps

        const uint32_t sb = sbase + (uint32_t)(k & 1) * STAGE_B;
#pragma unroll
        for (int kk = 0; kk < 4; kk++) {
            uint32_t ah[16], bh[8], bl[8];
#pragma unroll
            for (int mt = 0; mt < 4; mt++) {
                uint32_t sw = SWZ128((uint32_t)((warpM + mt * 16 + a_row) * 128 + kk * 32 + a_khalf));
                LDSM_X4(ah[mt*4+0], ah[mt*4+1], ah[mt*4+2], ah[mt*4+3], sb + OFF_A + sw);
            }
#pragma unroll
            for (int g = 0; g < 2; g++) {
                uint32_t sw = SWZ128((uint32_t)((warpN + g * 16 + b_row) * 128 + kk * 32 + b_khalf));
                LDSM_X4(bh[g*4+0], bh[g*4+1], bh[g*4+2], bh[g*4+3], sb + OFF_BH + sw);
                LDSM_X4(bl[g*4+0], bl[g*4+1], bl[g*4+2], bl[g*4+3], sb + OFF_BL + sw);
            }
            // term-major: same-acc reuse is 16 MMAs apart
#pragma unroll
            for (int mt = 0; mt < 4; mt++)
#pragma unroll
                for (int nt = 0; nt < 4; nt++) {
                    float* c = acc[mt][nt];
                    MMA_FP16(c[0], c[1], c[2], c[3],
                             ah[mt*4+0], ah[mt*4+1], ah[mt*4+2], ah[mt*4+3],
                             bh[nt*2+0], bh[nt*2+1]);
                }
#pragma unroll
            for (int mt = 0; mt < 4; mt++)
#pragma unroll
                for (int nt = 0; nt < 4; nt++) {
                    float* c = acc[mt][nt];
                    MMA_FP16(c[0], c[1], c[2], c[3],
                             ah[mt*4+0], ah[mt*4+1], ah[mt*4+2], ah[mt*4+3],
                             bl[nt*2+0], bl[nt*2+1]);
                }
        }

        __syncthreads();         // all warps done with buffer k&1
        if (k + 2 < NKS) load_stage((k + 2) * TBK, (uint32_t)(k & 1) * STAGE_B);
        cp_commit();             // unconditional: keeps wait_group accounting exact
    }

    // epilogue
    const int tq = lid >> 2;
    const int tr = (lid & 3) * 2;
#pragma unroll
    for (int mt = 0; mt < 4; mt++) {
#pragma unroll
        for (int nt = 0; nt < 4; nt++) {
            float* c = acc[mt][nt];
            int mrow = bm + warpM + mt * 16 + tq;
            int ncol = warpN + nt * 8 + tr;
            if (!bc) {
                float v0 = c[0], v1 = c[1], v2 = c[2], v3 = c[3];
                if (do_softplus) {
                    v0 = softplus_f(v0); v1 = softplus_f(v1);
                    v2 = softplus_f(v2); v3 = softplus_f(v3);
                }
                *reinterpret_cast<float2*>(&Out[(size_t)mrow * HID + bn + ncol]) = make_float2(v0, v1);
                *reinterpret_cast<float2*>(&Out[(size_t)(mrow + 8) * HID + bn + ncol]) = make_float2(v2, v3);
            } else if (ncol < 2 * NST) {
                *reinterpret_cast<float2*>(&OutBC[(size_t)mrow * (2 * NST) + ncol]) = make_float2(c[0], c[1]);
                *reinterpret_cast<float2*>(&OutBC[(size_t)(mrow + 8) * (2 * NST) + ncol]) = make_float2(c[2], c[3]);
            }
        }
    }
}

// ---------------------------------------------------------------------------
// Selective scan; writes fp16 y directly
// ---------------------------------------------------------------------------
#define CL 32
#define NCH (L_SEQ / CL)

__global__ __launch_bounds__(128) void scan_kernel(
    const float* __restrict__ dt_g, const float* __restrict__ bc_g,
    const float* __restrict__ x, const float* __restrict__ A_log,
    const float* __restrict__ Dp, __half* __restrict__ yh)
{
    __shared__ __align__(16) float sD[2][CL][32];
    __shared__ __align__(16) float sX[2][CL][32];
    __shared__ __align__(16) float sB[2][CL][16];
    __shared__ __align__(16) float sC[2][CL][16];

    const int tid = threadIdx.x;
    const int b = blockIdx.x >> 5;
    const int hbase = (blockIdx.x & 31) * 32;
    const int lane = tid & 31;
    const int w = tid >> 5;
    const int s = lane & 3;
    const int hl = (w << 3) | (lane >> 2);
    const int h = hbase + hl;

    float a2[4], hs[4];
#pragma unroll
    for (int i = 0; i < 4; i++) {
        a2[i] = -expf(A_log[s * 4 + i]) * 1.4426950408889634f;
        hs[i] = 0.0f;
    }
    const float Dv = Dp[h];

    const float* dt_b = dt_g + (size_t)b * L_SEQ * HID;
    const float* bc_b = bc_g + (size_t)b * L_SEQ * 2 * NST;
    const float* x_b  = x    + (size_t)b * L_SEQ * HID;
    __half* yh_b = yh + (size_t)b * L_SEQ * HID;

    auto load_chunk = [&](int c, int buf) {
        const int l0 = c * CL;
#pragma unroll
        for (int r = 0; r < 2; r++) {
            int idx = tid + r * 128;
            int row = idx >> 3;
            int col = (idx & 7) * 4;
            cp_async16(smem_u32(&sD[buf][row][col]),
                       &dt_b[(size_t)(l0 + row) * HID + hbase + col]);
            cp_async16(smem_u32(&sX[buf][row][col]),
                       &x_b[(size_t)(l0 + row) * HID + hbase + col]);
        }
        {
            int row = tid >> 2;
            int col = (tid & 3) * 4;
            cp_async16(smem_u32(&sB[buf][row][col]),
                       &bc_b[(size_t)(l0 + row) * 2 * NST + col]);
            cp_async16(smem_u32(&sC[buf][row][col]),
                       &bc_b[(size_t)(l0 + row) * 2 * NST + NST + col]);
        }
    };

    load_chunk(0, 0);
    cp_commit();

    int buf = 0;
    for (int c = 0; c < NCH; c++) {
        if (c + 1 < NCH) load_chunk(c + 1, buf ^ 1);
        cp_commit();
        cp_wait1();
        __syncthreads();

        const int l0 = c * CL;
#pragma unroll 8
        for (int li = 0; li < CL; li++) {
            float dt = sD[buf][li][hl];
            float xv = sX[buf][li][hl];
            float4 Bv = *reinterpret_cast<const float4*>(&sB[buf][li][s * 4]);
            float4 Cv = *reinterpret_cast<const float4*>(&sC[buf][li][s * 4]);
            float dx = dt * xv;

            float yv;
            hs[0] = fmaf(ex2_approx(dt * a2[0]), hs[0], dx * Bv.x); yv = hs[0] * Cv.x;
            hs[1] = fmaf(ex2_approx(dt * a2[1]), hs[1], dx * Bv.y); yv = fmaf(hs[1], Cv.y, yv);
            hs[2] = fmaf(ex2_approx(dt * a2[2]), hs[2], dx * Bv.z); yv = fmaf(hs[2], Cv.z, yv);
            hs[3] = fmaf(ex2_approx(dt * a2[3]), hs[3], dx * Bv.w); yv = fmaf(hs[3], Cv.w, yv);

            yv += __shfl_xor_sync(0xffffffffu, yv, 1);
            yv += __shfl_xor_sync(0xffffffffu, yv, 2);

            if (s == 0) {
                float yy = fmaf(Dv, xv, yv);
                yh_b[(size_t)(l0 + li) * HID + h] = __float2half_rn(yy);
            }
        }
        __syncthreads();
        buf ^= 1;
    }
}

// ---------------------------------------------------------------------------
// launch
// ---------------------------------------------------------------------------
extern "C" void kernel_launch(void* const* d_in, const int* in_sizes, int n_in,
                              void* d_out, int out_size)
{
    const float* x     = (const float*)d_in[0];
    const float* Wx    = (const float*)d_in[1];
    const float* A_log = (const float*)d_in[2];
    const float* D     = (const float*)d_in[3];
    const float* Wout  = (const float*)d_in[4];
    float* out = (float*)d_out;

    __half *xh, *yh, *wdhi, *wdlo, *wohi, *wolo, *wbchi, *wbclo;
    float *dt_p, *bc_p;
    cudaGetSymbolAddress((void**)&xh, g_xh);
    cudaGetSymbolAddress((void**)&yh, g_yh);
    cudaGetSymbolAddress((void**)&wdhi, g_wdhi);
    cudaGetSymbolAddress((void**)&wdlo, g_wdlo);
    cudaGetSymbolAddress((void**)&wohi, g_wohi);
    cudaGetSymbolAddress((void**)&wolo, g_wolo);
    cudaGetSymbolAddress((void**)&wbchi, g_wbchi);
    cudaGetSymbolAddress((void**)&wbclo, g_wbclo);
    cudaGetSymbolAddress((void**)&dt_p, g_dt);
    cudaGetSymbolAddress((void**)&bc_p, g_bc);

    cudaFuncSetAttribute(gemm_fp16_mma, cudaFuncAttributeMaxDynamicSharedMemorySize, SMEM_TOTAL_G);

    // converts / splits
    {
        int n4 = MROWS * HID / 4;
        conv_fp16<<<(n4 + 255) / 256, 256>>>(x, xh, n4);
        int w4 = HID * HID / 4;
        split_fp16<<<(w4 + 255) / 256, 256>>>(Wx + 2 * NST * HID, wdhi, wdlo, w4);
        split_fp16<<<(w4 + 255) / 256, 256>>>(Wout, wohi, wolo, w4);
        int bc4 = 2 * NST * HID / 4;
        split_fp16<<<(bc4 + 255) / 256, 256>>>(Wx, wbchi, wbclo, bc4);
    }

    // GEMM1: dt = softplus(x @ Wdelta^T), bc = x @ Wbc^T (col block 8)
    gemm_fp16_mma<<<dim3(9, MROWS / 128), 256, SMEM_TOTAL_G>>>(
        xh, wdhi, wdlo, wbchi, wbclo, dt_p, bc_p, 1);

    // selective scan (writes y as fp16)
    scan_kernel<<<BATCH * (HID / 32), 128>>>(dt_p, bc_p, x, A_log, D, yh);

    // GEMM2: out = y @ Wout^T
    gemm_fp16_mma<<<dim3(8, MROWS / 128), 256, SMEM_TOTAL_G>>>(
        yh, wohi, wolo, nullptr, nullptr, out, nullptr, 0);
}

// round 15
// speedup vs baseline: 4.0114x; 1.2732x over previous
#include <cuda_runtime.h>
#include <cuda_fp16.h>
#include <cstdint>

// Problem constants
#define BATCH 4
#define L_SEQ 2048
#define HID   1024
#define NST   16
#define MROWS (BATCH * L_SEQ) // 8192

// ---------------------------------------------------------------------------
// Device-global scratch (zero-initialized; no allocation allowed)
// ---------------------------------------------------------------------------
__device__ __half g_xh [(size_t)MROWS * HID];     // x in fp16
__device__ __half g_yh [(size_t)MROWS * HID];     // scan output in fp16
__device__ __half g_wd [(size_t)HID * HID];       // Wx rows 32..1055 (delta), fp16
__device__ __half g_wo [(size_t)HID * HID];       // Wout, fp16
__device__ __half g_wbc[(size_t)128 * HID];       // Wx rows 0..31 zero-padded, fp16
__device__ float g_dt[(size_t)MROWS * HID];       // softplus(delta)
__device__ float g_bc[(size_t)MROWS * 2 * NST];   // B,C columns

// ---------------------------------------------------------------------------
// helpers
// ---------------------------------------------------------------------------
__device__ __forceinline__ uint32_t smem_u32(const void* p) {
    return (uint32_t)__cvta_generic_to_shared(p);
}
__device__ __forceinline__ void cp_async16(uint32_t dst, const void* src) {
    asm volatile("cp.async.cg.shared.global [%0], [%1], 16;\n" :: "r"(dst), "l"(src) : "memory");
}
__device__ __forceinline__ void cp_commit() {
    asm volatile("cp.async.commit_group;\n" ::: "memory");
}
__device__ __forceinline__ void cp_wait1() {
    asm volatile("cp.async.wait_group 1;\n" ::: "memory");
}
__device__ __forceinline__ float ex2_approx(float v) {
    float r;
    asm("ex2.approx.ftz.f32 %0, %1;" : "=f"(r) : "f"(v));
    return r;
}
__device__ __forceinline__ float softplus_f(float z) {
    return log1pf(expf(-fabsf(z))) + fmaxf(z, 0.0f);
}

// SW128 swizzle for 128-byte rows (TBK=64 fp16)
#define SWZ128(off) ((off) ^ (((off) >> 3) & 0x70))

#define LDSM_X4(r0, r1, r2, r3, addr) \
    asm volatile("ldmatrix.sync.aligned.m8n8.x4.shared.b16 {%0,%1,%2,%3}, [%4];" \
        : "=r"(r0), "=r"(r1), "=r"(r2), "=r"(r3) : "r"(addr))

#define MMA_FP16(c0, c1, c2, c3, a0, a1, a2, a3, b0, b1) \
    asm volatile("mma.sync.aligned.m16n8k16.row.col.f32.f16.f16.f32 " \
        "{%0,%1,%2,%3}, {%4,%5,%6,%7}, {%8,%9}, {%0,%1,%2,%3};" \
        : "+f"(c0), "+f"(c1), "+f"(c2), "+f"(c3) \
        : "r"(a0), "r"(a1), "r"(a2), "r"(a3), "r"(b0), "r"(b1))

// ---------------------------------------------------------------------------
// fp32 -> fp16 convert
// ---------------------------------------------------------------------------
__global__ __launch_bounds__(256) void conv_fp16(
    const float* __restrict__ s, __half* __restrict__ d, int n4)
{
    int i = blockIdx.x * blockDim.x + threadIdx.x;
    if (i >= n4) return;
    float4 v = reinterpret_cast<const float4*>(s)[i];
    __half2* D = reinterpret_cast<__half2*>(d);
    D[2 * i]     = __floats2half2_rn(v.x, v.y);
    D[2 * i + 1] = __floats2half2_rn(v.z, v.w);
}

// ---------------------------------------------------------------------------
// fp16 GEMM via mma.sync (NT): Out = A * B^T, fp32 accumulate (~5e-4 accuracy).
// CTA tile 128x128x64, 256 threads (8 warps, 2x4), warp tile 64x32.
// 3-stage cp.async pipeline, 32 KB/stage -> 96 KB smem -> 2 CTAs/SM.
// Single sync per stage: load k+2 issued before compute of stage k.
// blockIdx.x == 8 (GEMM1 only): B/C projection against zero-padded Wbc.
// ---------------------------------------------------------------------------
#define TBK 64
#define NKS (HID / TBK)               // 16 K-stages
#define T128_B (128 * 128)            // 16384 bytes (128 rows x 128B)
#define OFF_A  0
#define OFF_B  (T128_B)
#define STAGE_B (2 * T128_B)          // 32768
#define NSTAGE 3
#define SMEM_TOTAL_G (NSTAGE * STAGE_B)  // 98304

__global__ __launch_bounds__(256, 2) void gemm_fp16_mma(
    const __half* __restrict__ A, const __half* __restrict__ B,
    const __half* __restrict__ BC,
    float* __restrict__ Out, float* __restrict__ OutBC, int do_softplus)
{
    extern __shared__ __align__(1024) uint8_t dsm[];
    const uint32_t sbase = smem_u32(dsm);
    const int t = threadIdx.x;
    const int lid = t & 31;
    const int wid = t >> 5;
    const int warpM = (wid >> 2) * 64;   // 0,64
    const int warpN = (wid & 3) * 32;    // 0..96
    const int bm = blockIdx.y * 128;
    const bool bc = (blockIdx.x == 8);
    const int bn = bc ? 0 : blockIdx.x * 128;

    const __half* srcs[2];
    srcs[0] = A + (size_t)bm * HID;
    srcs[1] = (bc ? BC : B + (size_t)bn * HID);

    // stage loader: 2 tiles x (128 rows x 8 segs of 16B) = 2048 chunks / 256 thr
    auto load_stage = [&](int k0, uint32_t soff) {
#pragma unroll
        for (int tile = 0; tile < 2; tile++) {
            const __half* sp = srcs[tile] + k0;
            uint32_t dbase = sbase + soff + tile * T128_B;
#pragma unroll
            for (int i = 0; i < 4; i++) {
                int u = t + i * 256;          // 0..1023
                int row = u >> 3;             // 0..127
                int seg = u & 7;
                uint32_t off = SWZ128((uint32_t)(row * 128 + seg * 16));
                cp_async16(dbase + off, sp + (size_t)row * HID + seg * 8);
            }
        }
    };

    float acc[4][4][4];
#pragma unroll
    for (int i = 0; i < 4; i++)
#pragma unroll
        for (int j = 0; j < 4; j++)
#pragma unroll
            for (int q = 0; q < 4; q++) acc[i][j][q] = 0.0f;

    // lane addressing
    const int a_row = (lid & 15);
    const int a_khalf = (lid >> 4) << 4;
    const int b_q = lid >> 3;
    const int b_row = ((b_q >> 1) << 3) + (lid & 7);
    const int b_khalf = (b_q & 1) << 4;

    load_stage(0, 0);
    cp_commit();
    load_stage(TBK, STAGE_B);
    cp_commit();

    for (int k = 0; k < NKS; k++) {
        cp_wait1();              // stage k's group complete (k+1 may pend)
        __syncthreads();         // data visible + all warps done with stage k-1

        // issue stage k+2 into buffer (k+2)%3 == (k-1)%3 (freed by the sync)
        if (k + 2 < NKS) load_stage((k + 2) * TBK, (uint32_t)((k + 2) % NSTAGE) * STAGE_B);
        cp_commit();             // unconditional: keeps wait_group accounting exact

        const uint32_t sb = sbase + (uint32_t)(k % NSTAGE) * STAGE_B;
#pragma unroll
        for (int kk = 0; kk < 4; kk++) {
            uint32_t ah[16], bh[8];
#pragma unroll
            for (int mt = 0; mt < 4; mt++) {
                uint32_t sw = SWZ128((uint32_t)((warpM + mt * 16 + a_row) * 128 + kk * 32 + a_khalf));
                LDSM_X4(ah[mt*4+0], ah[mt*4+1], ah[mt*4+2], ah[mt*4+3], sb + OFF_A + sw);
            }
#pragma unroll
            for (int g = 0; g < 2; g++) {
                uint32_t sw = SWZ128((uint32_t)((warpN + g * 16 + b_row) * 128 + kk * 32 + b_khalf));
                LDSM_X4(bh[g*4+0], bh[g*4+1], bh[g*4+2], bh[g*4+3], sb + OFF_B + sw);
            }
#pragma unroll
            for (int mt = 0; mt < 4; mt++)
#pragma unroll
                for (int nt = 0; nt < 4; nt++) {
                    float* c = acc[mt][nt];
                    MMA_FP16(c[0], c[1], c[2], c[3],
                             ah[mt*4+0], ah[mt*4+1], ah[mt*4+2], ah[mt*4+3],
                             bh[nt*2+0], bh[nt*2+1]);
                }
        }
    }

    // epilogue
    const int tq = lid >> 2;
    const int tr = (lid & 3) * 2;
#pragma unroll
    for (int mt = 0; mt < 4; mt++) {
#pragma unroll
        for (int nt = 0; nt < 4; nt++) {
            float* c = acc[mt][nt];
            int mrow = bm + warpM + mt * 16 + tq;
            int ncol = warpN + nt * 8 + tr;
            if (!bc) {
                float v0 = c[0], v1 = c[1], v2 = c[2], v3 = c[3];
                if (do_softplus) {
                    v0 = softplus_f(v0); v1 = softplus_f(v1);
                    v2 = softplus_f(v2); v3 = softplus_f(v3);
                }
                *reinterpret_cast<float2*>(&Out[(size_t)mrow * HID + bn + ncol]) = make_float2(v0, v1);
                *reinterpret_cast<float2*>(&Out[(size_t)(mrow + 8) * HID + bn + ncol]) = make_float2(v2, v3);
            } else if (ncol < 2 * NST) {
                *reinterpret_cast<float2*>(&OutBC[(size_t)mrow * (2 * NST) + ncol]) = make_float2(c[0], c[1]);
                *reinterpret_cast<float2*>(&OutBC[(size_t)(mrow + 8) * (2 * NST) + ncol]) = make_float2(c[2], c[3]);
            }
        }
    }
}

// ---------------------------------------------------------------------------
// Selective scan; writes fp16 y directly
// ---------------------------------------------------------------------------
#define CL 32
#define NCH (L_SEQ / CL)

__global__ __launch_bounds__(128) void scan_kernel(
    const float* __restrict__ dt_g, const float* __restrict__ bc_g,
    const float* __restrict__ x, const float* __restrict__ A_log,
    const float* __restrict__ Dp, __half* __restrict__ yh)
{
    __shared__ __align__(16) float sD[2][CL][32];
    __shared__ __align__(16) float sX[2][CL][32];
    __shared__ __align__(16) float sB[2][CL][16];
    __shared__ __align__(16) float sC[2][CL][16];

    const int tid = threadIdx.x;
    const int b = blockIdx.x >> 5;
    const int hbase = (blockIdx.x & 31) * 32;
    const int lane = tid & 31;
    const int w = tid >> 5;
    const int s = lane & 3;
    const int hl = (w << 3) | (lane >> 2);
    const int h = hbase + hl;

    float a2[4], hs[4];
#pragma unroll
    for (int i = 0; i < 4; i++) {
        a2[i] = -expf(A_log[s * 4 + i]) * 1.4426950408889634f;
        hs[i] = 0.0f;
    }
    const float Dv = Dp[h];

    const float* dt_b = dt_g + (size_t)b * L_SEQ * HID;
    const float* bc_b = bc_g + (size_t)b * L_SEQ * 2 * NST;
    const float* x_b  = x    + (size_t)b * L_SEQ * HID;
    __half* yh_b = yh + (size_t)b * L_SEQ * HID;

    auto load_chunk = [&](int c, int buf) {
        const int l0 = c * CL;
#pragma unroll
        for (int r = 0; r < 2; r++) {
            int idx = tid + r * 128;
            int row = idx >> 3;
            int col = (idx & 7) * 4;
            cp_async16(smem_u32(&sD[buf][row][col]),
                       &dt_b[(size_t)(l0 + row) * HID + hbase + col]);
            cp_async16(smem_u32(&sX[buf][row][col]),
                       &x_b[(size_t)(l0 + row) * HID + hbase + col]);
        }
        {
            int row = tid >> 2;
            int col = (tid & 3) * 4;
            cp_async16(smem_u32(&sB[buf][row][col]),
                       &bc_b[(size_t)(l0 + row) * 2 * NST + col]);
            cp_async16(smem_u32(&sC[buf][row][col]),
                       &bc_b[(size_t)(l0 + row) * 2 * NST + NST + col]);
        }
    };

    load_chunk(0, 0);
    cp_commit();

    int buf = 0;
    for (int c = 0; c < NCH; c++) {
        if (c + 1 < NCH) load_chunk(c + 1, buf ^ 1);
        cp_commit();
        cp_wait1();
        __syncthreads();

        const int l0 = c * CL;
#pragma unroll 8
        for (int li = 0; li < CL; li++) {
            float dt = sD[buf][li][hl];
            float xv = sX[buf][li][hl];
            float4 Bv = *reinterpret_cast<const float4*>(&sB[buf][li][s * 4]);
            float4 Cv = *reinterpret_cast<const float4*>(&sC[buf][li][s * 4]);
            float dx = dt * xv;

            float yv;
            hs[0] = fmaf(ex2_approx(dt * a2[0]), hs[0], dx * Bv.x); yv = hs[0] * Cv.x;
            hs[1] = fmaf(ex2_approx(dt * a2[1]), hs[1], dx * Bv.y); yv = fmaf(hs[1], Cv.y, yv);
            hs[2] = fmaf(ex2_approx(dt * a2[2]), hs[2], dx * Bv.z); yv = fmaf(hs[2], Cv.z, yv);
            hs[3] = fmaf(ex2_approx(dt * a2[3]), hs[3], dx * Bv.w); yv = fmaf(hs[3], Cv.w, yv);

            yv += __shfl_xor_sync(0xffffffffu, yv, 1);
            yv += __shfl_xor_sync(0xffffffffu, yv, 2);

            if (s == 0) {
                float yy = fmaf(Dv, xv, yv);
                yh_b[(size_t)(l0 + li) * HID + h] = __float2half_rn(yy);
            }
        }
        __syncthreads();
        buf ^= 1;
    }
}

// ---------------------------------------------------------------------------
// launch
// ---------------------------------------------------------------------------
extern "C" void kernel_launch(void* const* d_in, const int* in_sizes, int n_in,
                              void* d_out, int out_size)
{
    const float* x     = (const float*)d_in[0];
    const float* Wx    = (const float*)d_in[1];
    const float* A_log = (const float*)d_in[2];
    const float* D     = (const float*)d_in[3];
    const float* Wout  = (const float*)d_in[4];
    float* out = (float*)d_out;

    __half *xh, *yh, *wd, *wo, *wbc;
    float *dt_p, *bc_p;
    cudaGetSymbolAddress((void**)&xh, g_xh);
    cudaGetSymbolAddress((void**)&yh, g_yh);
    cudaGetSymbolAddress((void**)&wd, g_wd);
    cudaGetSymbolAddress((void**)&wo, g_wo);
    cudaGetSymbolAddress((void**)&wbc, g_wbc);
    cudaGetSymbolAddress((void**)&dt_p, g_dt);
    cudaGetSymbolAddress((void**)&bc_p, g_bc);

    cudaFuncSetAttribute(gemm_fp16_mma, cudaFuncAttributeMaxDynamicSharedMemorySize, SMEM_TOTAL_G);

    // converts
    {
        int n4 = MROWS * HID / 4;
        conv_fp16<<<(n4 + 255) / 256, 256>>>(x, xh, n4);
        int w4 = HID * HID / 4;
        conv_fp16<<<(w4 + 255) / 256, 256>>>(Wx + 2 * NST * HID, wd, w4);
        conv_fp16<<<(w4 + 255) / 256, 256>>>(Wout, wo, w4);
        int bc4 = 2 * NST * HID / 4;
        conv_fp16<<<(bc4 + 255) / 256, 256>>>(Wx, wbc, bc4);
    }

    // GEMM1: dt = softplus(x @ Wdelta^T), bc = x @ Wbc^T (col block 8)
    gemm_fp16_mma<<<dim3(9, MROWS / 128), 256, SMEM_TOTAL_G>>>(
        xh, wd, wbc, dt_p, bc_p, 1);

    // selective scan (writes y as fp16)
    scan_kernel<<<BATCH * (HID / 32), 128>>>(dt_p, bc_p, x, A_log, D, yh);

    // GEMM2: out = y @ Wout^T
    gemm_fp16_mma<<<dim3(8, MROWS / 128), 256, SMEM_TOTAL_G>>>(
        yh, wo, nullptr, out, nullptr, 0);
}

// round 17
// speedup vs baseline: 4.3361x; 1.0809x over previous
#include <cuda_runtime.h>
#include <cuda_fp16.h>
#include <cstdint>

// Problem constants
#define BATCH 4
#define L_SEQ 2048
#define HID   1024
#define NST   16
#define MROWS (BATCH * L_SEQ) // 8192

// Chunked scan
#define CHL   256                 // chunk length
#define NCHK  (L_SEQ / CHL)       // 8 chunks
#define CL    32                  // staging sub-chunk
#define NSUB  (CHL / CL)          // 8 sub-chunks per chunk

// ---------------------------------------------------------------------------
// Device-global scratch (zero-initialized; no allocation allowed)
// ---------------------------------------------------------------------------
__device__ __half g_xh [(size_t)MROWS * HID];     // x in fp16
__device__ __half g_yh [(size_t)MROWS * HID];     // scan output in fp16
__device__ __half g_wd [(size_t)HID * HID];       // Wx rows 32..1055 (delta), fp16
__device__ __half g_wo [(size_t)HID * HID];       // Wout, fp16
__device__ __half g_wbc[(size_t)128 * HID];       // Wx rows 0..31 zero-padded, fp16
__device__ float g_dt[(size_t)MROWS * HID];       // softplus(delta)
__device__ float g_bc[(size_t)MROWS * 2 * NST];   // B,C columns
__device__ float4 g_hS[(size_t)BATCH * NCHK * HID * 4];  // per-chunk local scan result
__device__ float4 g_hI[(size_t)BATCH * NCHK * HID * 4];  // per-chunk initial state
__device__ float  g_sdt[(size_t)BATCH * NCHK * HID];     // per-chunk sum of dt

// ---------------------------------------------------------------------------
// helpers
// ---------------------------------------------------------------------------
__device__ __forceinline__ uint32_t smem_u32(const void* p) {
    return (uint32_t)__cvta_generic_to_shared(p);
}
__device__ __forceinline__ void cp_async16(uint32_t dst, const void* src) {
    asm volatile("cp.async.cg.shared.global [%0], [%1], 16;\n" :: "r"(dst), "l"(src) : "memory");
}
__device__ __forceinline__ void cp_commit() {
    asm volatile("cp.async.commit_group;\n" ::: "memory");
}
__device__ __forceinline__ void cp_wait1() {
    asm volatile("cp.async.wait_group 1;\n" ::: "memory");
}
__device__ __forceinline__ float ex2_approx(float v) {
    float r;
    asm("ex2.approx.ftz.f32 %0, %1;" : "=f"(r) : "f"(v));
    return r;
}
__device__ __forceinline__ float softplus_f(float z) {
    return log1pf(expf(-fabsf(z))) + fmaxf(z, 0.0f);
}

// SW128 swizzle for 128-byte rows (TBK=64 fp16)
#define SWZ128(off) ((off) ^ (((off) >> 3) & 0x70))

#define LDSM_X4(r0, r1, r2, r3, addr) \
    asm volatile("ldmatrix.sync.aligned.m8n8.x4.shared.b16 {%0,%1,%2,%3}, [%4];" \
        : "=r"(r0), "=r"(r1), "=r"(r2), "=r"(r3) : "r"(addr))

#define MMA_FP16(c0, c1, c2, c3, a0, a1, a2, a3, b0, b1) \
    asm volatile("mma.sync.aligned.m16n8k16.row.col.f32.f16.f16.f32 " \
        "{%0,%1,%2,%3}, {%4,%5,%6,%7}, {%8,%9}, {%0,%1,%2,%3};" \
        : "+f"(c0), "+f"(c1), "+f"(c2), "+f"(c3) \
        : "r"(a0), "r"(a1), "r"(a2), "r"(a3), "r"(b0), "r"(b1))

// ---------------------------------------------------------------------------
// Merged fp32 -> fp16 converts: x, Wdelta, Wout, Wbc in one launch
// ---------------------------------------------------------------------------
#define X4SZ  (MROWS * HID / 4)          // 2097152
#define W4SZ  (HID * HID / 4)            // 262144
#define BC4SZ (2 * NST * HID / 4)        // 8192
#define CONV_TOTAL (X4SZ + 2 * W4SZ + BC4SZ)

__global__ __launch_bounds__(256) void conv_all(
    const float* __restrict__ x, const float* __restrict__ Wx,
    const float* __restrict__ Wout,
    __half* __restrict__ xh, __half* __restrict__ wd,
    __half* __restrict__ wo, __half* __restrict__ wbc)
{
    int i = blockIdx.x * blockDim.x + threadIdx.x;
    if (i >= CONV_TOTAL) return;
    const float* s;
    __half* d;
    int j;
    if (i < X4SZ) {
        s = x; d = xh; j = i;
    } else if (i < X4SZ + W4SZ) {
        s = Wx + 2 * NST * HID; d = wd; j = i - X4SZ;
    } else if (i < X4SZ + 2 * W4SZ) {
        s = Wout; d = wo; j = i - X4SZ - W4SZ;
    } else {
        s = Wx; d = wbc; j = i - X4SZ - 2 * W4SZ;
    }
    float4 v = reinterpret_cast<const float4*>(s)[j];
    __half2* D = reinterpret_cast<__half2*>(d);
    D[2 * j]     = __floats2half2_rn(v.x, v.y);
    D[2 * j + 1] = __floats2half2_rn(v.z, v.w);
}

// ---------------------------------------------------------------------------
// fp16 GEMM via mma.sync (NT): Out = A * B^T, fp32 accumulate (~5e-4 accuracy).
// CTA tile 128x128x64, 256 threads (8 warps, 2x4), warp tile 64x32.
// 3-stage cp.async pipeline, 32 KB/stage -> 96 KB smem -> 2 CTAs/SM.
// blockIdx.x == 8 (GEMM1 only): B/C projection against zero-padded Wbc.
// ---------------------------------------------------------------------------
#define TBK 64
#define NKS (HID / TBK)               // 16 K-stages
#define T128_B (128 * 128)            // 16384 bytes
#define OFF_A  0
#define OFF_B  (T128_B)
#define STAGE_B (2 * T128_B)          // 32768
#define NSTAGE 3
#define SMEM_TOTAL_G (NSTAGE * STAGE_B)  // 98304

__global__ __launch_bounds__(256, 2) void gemm_fp16_mma(
    const __half* __restrict__ A, const __half* __restrict__ B,
    const __half* __restrict__ BC,
    float* __restrict__ Out, float* __restrict__ OutBC, int do_softplus)
{
    extern __shared__ __align__(1024) uint8_t dsm[];
    const uint32_t sbase = smem_u32(dsm);
    const int t = threadIdx.x;
    const int lid = t & 31;
    const int wid = t >> 5;
    const int warpM = (wid >> 2) * 64;
    const int warpN = (wid & 3) * 32;
    const int bm = blockIdx.y * 128;
    const bool bc = (blockIdx.x == 8);
    const int bn = bc ? 0 : blockIdx.x * 128;

    const __half* srcs[2];
    srcs[0] = A + (size_t)bm * HID;
    srcs[1] = (bc ? BC : B + (size_t)bn * HID);

    auto load_stage = [&](int k0, uint32_t soff) {
#pragma unroll
        for (int tile = 0; tile < 2; tile++) {
            const __half* sp = srcs[tile] + k0;
            uint32_t dbase = sbase + soff + tile * T128_B;
#pragma unroll
            for (int i = 0; i < 4; i++) {
                int u = t + i * 256;
                int row = u >> 3;
                int seg = u & 7;
                uint32_t off = SWZ128((uint32_t)(row * 128 + seg * 16));
                cp_async16(dbase + off, sp + (size_t)row * HID + seg * 8);
            }
        }
    };

    float acc[4][4][4];
#pragma unroll
    for (int i = 0; i < 4; i++)
#pragma unroll
        for (int j = 0; j < 4; j++)
#pragma unroll
            for (int q = 0; q < 4; q++) acc[i][j][q] = 0.0f;

    const int a_row = (lid & 15);
    const int a_khalf = (lid >> 4) << 4;
    const int b_q = lid >> 3;
    const int b_row = ((b_q >> 1) << 3) + (lid & 7);
    const int b_khalf = (b_q & 1) << 4;

    load_stage(0, 0);
    cp_commit();
    load_stage(TBK, STAGE_B);
    cp_commit();

    for (int k = 0; k < NKS; k++) {
        cp_wait1();
        __syncthreads();

        if (k + 2 < NKS) load_stage((k + 2) * TBK, (uint32_t)((k + 2) % NSTAGE) * STAGE_B);
        cp_commit();

        const uint32_t sb = sbase + (uint32_t)(k % NSTAGE) * STAGE_B;
#pragma unroll
        for (int kk = 0; kk < 4; kk++) {
            uint32_t ah[16], bh[8];
#pragma unroll
            for (int mt = 0; mt < 4; mt++) {
                uint32_t sw = SWZ128((uint32_t)((warpM + mt * 16 + a_row) * 128 + kk * 32 + a_khalf));
                LDSM_X4(ah[mt*4+0], ah[mt*4+1], ah[mt*4+2], ah[mt*4+3], sb + OFF_A + sw);
            }
#pragma unroll
            for (int g = 0; g < 2; g++) {
                uint32_t sw = SWZ128((uint32_t)((warpN + g * 16 + b_row) * 128 + kk * 32 + b_khalf));
                LDSM_X4(bh[g*4+0], bh[g*4+1], bh[g*4+2], bh[g*4+3], sb + OFF_B + sw);
            }
#pragma unroll
            for (int mt = 0; mt < 4; mt++)
#pragma unroll
                for (int nt = 0; nt < 4; nt++) {
                    float* c = acc[mt][nt];
                    MMA_FP16(c[0], c[1], c[2], c[3],
                             ah[mt*4+0], ah[mt*4+1], ah[mt*4+2], ah[mt*4+3],
                             bh[nt*2+0], bh[nt*2+1]);
                }
        }
    }

    const int tq = lid >> 2;
    const int tr = (lid & 3) * 2;
#pragma unroll
    for (int mt = 0; mt < 4; mt++) {
#pragma unroll
        for (int nt = 0; nt < 4; nt++) {
            float* c = acc[mt][nt];
            int mrow = bm + warpM + mt * 16 + tq;
            int ncol = warpN + nt * 8 + tr;
            if (!bc) {
                float v0 = c[0], v1 = c[1], v2 = c[2], v3 = c[3];
                if (do_softplus) {
                    v0 = softplus_f(v0); v1 = softplus_f(v1);
                    v2 = softplus_f(v2); v3 = softplus_f(v3);
                }
                *reinterpret_cast<float2*>(&Out[(size_t)mrow * HID + bn + ncol]) = make_float2(v0, v1);
                *reinterpret_cast<float2*>(&Out[(size_t)(mrow + 8) * HID + bn + ncol]) = make_float2(v2, v3);
            } else if (ncol < 2 * NST) {
                *reinterpret_cast<float2*>(&OutBC[(size_t)mrow * (2 * NST) + ncol]) = make_float2(c[0], c[1]);
                *reinterpret_cast<float2*>(&OutBC[(size_t)(mrow + 8) * (2 * NST) + ncol]) = make_float2(c[2], c[3]);
            }
        }
    }
}

// ---------------------------------------------------------------------------
// Chunked selective scan, pass A (mode=0) and pass C (mode=1).
// Block: one (batch, 32-h group, chunk). 128 threads: 32 h x 4 s-groups.
// Pass A: scan 256 steps from h=0; store final h (g_hS) and sum(dt) (g_sdt).
// Pass C: load h_init from g_hI, scan 256 steps, emit y (fp16).
// ---------------------------------------------------------------------------
__global__ __launch_bounds__(128) void scan_chunk(
    const float* __restrict__ dt_g, const float* __restrict__ bc_g,
    const float* __restrict__ x, const float* __restrict__ A_log,
    const float* __restrict__ Dp, __half* __restrict__ yh, int mode)
{
    __shared__ __align__(16) float sD[2][CL][32];
    __shared__ __align__(16) float sX[2][CL][32];
    __shared__ __align__(16) float sB[2][CL][16];
    __shared__ __align__(16) float sC[2][CL][16];

    const int tid = threadIdx.x;
    const int chunk = blockIdx.x & (NCHK - 1);
    const int hgrp  = (blockIdx.x >> 3) & 31;
    const int b     = blockIdx.x >> 8;
    const int hbase = hgrp * 32;
    const int lane = tid & 31;
    const int w = tid >> 5;
    const int s = lane & 3;
    const int hl = (w << 3) | (lane >> 2);
    const int h = hbase + hl;
    const int chunk_l0 = chunk * CHL;

    float a2[4], hs[4];
#pragma unroll
    for (int i = 0; i < 4; i++)
        a2[i] = -expf(A_log[s * 4 + i]) * 1.4426950408889634f;

    if (mode == 0) {
#pragma unroll
        for (int i = 0; i < 4; i++) hs[i] = 0.0f;
    } else {
        float4 hi = g_hI[(((size_t)(b * NCHK + chunk) * HID + h) << 2) + s];
        hs[0] = hi.x; hs[1] = hi.y; hs[2] = hi.z; hs[3] = hi.w;
    }
    const float Dv = Dp[h];

    const float* dt_b = dt_g + (size_t)b * L_SEQ * HID;
    const float* bc_b = bc_g + (size_t)b * L_SEQ * 2 * NST;
    const float* x_b  = x    + (size_t)b * L_SEQ * HID;
    __half* yh_b = yh + (size_t)b * L_SEQ * HID;

    auto load_chunk = [&](int c, int buf) {
        const int l0 = chunk_l0 + c * CL;
#pragma unroll
        for (int r = 0; r < 2; r++) {
            int idx = tid + r * 128;
            int row = idx >> 3;
            int col = (idx & 7) * 4;
            cp_async16(smem_u32(&sD[buf][row][col]),
                       &dt_b[(size_t)(l0 + row) * HID + hbase + col]);
            cp_async16(smem_u32(&sX[buf][row][col]),
                       &x_b[(size_t)(l0 + row) * HID + hbase + col]);
        }
        {
            int row = tid >> 2;
            int col = (tid & 3) * 4;
            cp_async16(smem_u32(&sB[buf][row][col]),
                       &bc_b[(size_t)(l0 + row) * 2 * NST + col]);
            if (mode)
                cp_async16(smem_u32(&sC[buf][row][col]),
                           &bc_b[(size_t)(l0 + row) * 2 * NST + NST + col]);
        }
    };

    load_chunk(0, 0);
    cp_commit();

    float dtsum = 0.0f;
    int buf = 0;
    for (int c = 0; c < NSUB; c++) {
        if (c + 1 < NSUB) load_chunk(c + 1, buf ^ 1);
        cp_commit();
        cp_wait1();
        __syncthreads();

        const int l0 = chunk_l0 + c * CL;
#pragma unroll 8
        for (int li = 0; li < CL; li++) {
            float dt = sD[buf][li][hl];
            float xv = sX[buf][li][hl];
            float4 Bv = *reinterpret_cast<const float4*>(&sB[buf][li][s * 4]);
            float dx = dt * xv;
            dtsum += dt;

            hs[0] = fmaf(ex2_approx(dt * a2[0]), hs[0], dx * Bv.x);
            hs[1] = fmaf(ex2_approx(dt * a2[1]), hs[1], dx * Bv.y);
            hs[2] = fmaf(ex2_approx(dt * a2[2]), hs[2], dx * Bv.z);
            hs[3] = fmaf(ex2_approx(dt * a2[3]), hs[3], dx * Bv.w);

            if (mode) {
                float4 Cv = *reinterpret_cast<const float4*>(&sC[buf][li][s * 4]);
                float yv = hs[0] * Cv.x;
                yv = fmaf(hs[1], Cv.y, yv);
                yv = fmaf(hs[2], Cv.z, yv);
                yv = fmaf(hs[3], Cv.w, yv);
                yv += __shfl_xor_sync(0xffffffffu, yv, 1);
                yv += __shfl_xor_sync(0xffffffffu, yv, 2);
                if (s == 0) {
                    float yy = fmaf(Dv, xv, yv);
                    yh_b[(size_t)(l0 + li) * HID + h] = __float2half_rn(yy);
                }
            }
        }
        __syncthreads();
        buf ^= 1;
    }

    if (mode == 0) {
        size_t base = ((size_t)(b * NCHK + chunk) * HID + h);
        g_hS[(base << 2) + s] = make_float4(hs[0], hs[1], hs[2], hs[3]);
        if (s == 0) g_sdt[base] = dtsum;
    }
}

// ---------------------------------------------------------------------------
// Combine pass: serial over 8 chunks per (b, h, s-group).
// h_init[c] = P(c-1) * h_init[c-1] + S[c-1],  P_i = exp(A_i * sumdt)
// ---------------------------------------------------------------------------
__global__ __launch_bounds__(256) void scan_combine(const float* __restrict__ A_log)
{
    int gt = blockIdx.x * blockDim.x + threadIdx.x;   // 0 .. BATCH*HID*4-1
    if (gt >= BATCH * HID * 4) return;
    const int s = gt & 3;
    const int h = (gt >> 2) & (HID - 1);
    const int b = gt >> 12;

    float a2[4];
#pragma unroll
    for (int i = 0; i < 4; i++)
        a2[i] = -expf(A_log[s * 4 + i]) * 1.4426950408889634f;

    float h0 = 0.f, h1 = 0.f, h2 = 0.f, h3 = 0.f;
#pragma unroll
    for (int c = 0; c < NCHK; c++) {
        size_t base = ((size_t)(b * NCHK + c) * HID + h);
        g_hI[(base << 2) + s] = make_float4(h0, h1, h2, h3);
        float4 S = g_hS[(base << 2) + s];
        float sd = g_sdt[base];
        h0 = fmaf(ex2_approx(a2[0] * sd), h0, S.x);
        h1 = fmaf(ex2_approx(a2[1] * sd), h1, S.y);
        h2 = fmaf(ex2_approx(a2[2] * sd), h2, S.z);
        h3 = fmaf(ex2_approx(a2[3] * sd), h3, S.w);
    }
}

// ---------------------------------------------------------------------------
// launch
// ---------------------------------------------------------------------------
extern "C" void kernel_launch(void* const* d_in, const int* in_sizes, int n_in,
                              void* d_out, int out_size)
{
    const float* x     = (const float*)d_in[0];
    const float* Wx    = (const float*)d_in[1];
    const float* A_log = (const float*)d_in[2];
    const float* D     = (const float*)d_in[3];
    const float* Wout  = (const float*)d_in[4];
    float* out = (float*)d_out;

    __half *xh, *yh, *wd, *wo, *wbc;
    float *dt_p, *bc_p;
    cudaGetSymbolAddress((void**)&xh, g_xh);
    cudaGetSymbolAddress((void**)&yh, g_yh);
    cudaGetSymbolAddress((void**)&wd, g_wd);
    cudaGetSymbolAddress((void**)&wo, g_wo);
    cudaGetSymbolAddress((void**)&wbc, g_wbc);
    cudaGetSymbolAddress((void**)&dt_p, g_dt);
    cudaGetSymbolAddress((void**)&bc_p, g_bc);

    cudaFuncSetAttribute(gemm_fp16_mma, cudaFuncAttributeMaxDynamicSharedMemorySize, SMEM_TOTAL_G);

    // merged converts (1 launch)
    conv_all<<<(CONV_TOTAL + 255) / 256, 256>>>(x, Wx, Wout, xh, wd, wo, wbc);

    // GEMM1: dt = softplus(x @ Wdelta^T), bc = x @ Wbc^T (col block 8)
    gemm_fp16_mma<<<dim3(9, MROWS / 128), 256, SMEM_TOTAL_G>>>(
        xh, wd, wbc, dt_p, bc_p, 1);

    // chunked scan: pass A (local scans) -> combine -> pass C (emit y)
    scan_chunk<<<BATCH * 32 * NCHK, 128>>>(dt_p, bc_p, x, A_log, D, yh, 0);
    scan_combine<<<(BATCH * HID * 4 + 255) / 256, 256>>>(A_log);
    scan_chunk<<<BATCH * 32 * NCHK, 128>>>(dt_p, bc_p, x, A_log, D, yh, 1);

    // GEMM2: out = y @ Wout^T
    gemm_fp16_mma<<<dim3(8, MROWS / 128), 256, SMEM_TOTAL_G>>>(
        yh, wo, nullptr, out, nullptr, 0);
}